// round 1
// baseline (speedup 1.0000x reference)
#include <cuda_runtime.h>
#include <math.h>

#define BB   2
#define TT   1024
#define CC   1024
#define NHH  16
#define DHH  64
#define LLAYERS 4
#define HFF_ 2816
#define MM   (BB*TT)          // 2048 rows

// ---------------- scratch (static device globals; no allocation allowed) ---
__device__ __align__(16) float g_h [MM*CC];        // residual stream
__device__ __align__(16) float g_a [MM*CC];        // rms-normed activations
__device__ __align__(16) float g_q [MM*CC];        // q projection
__device__ __align__(16) float g_kv[MM*2*CC];      // k|v projection
__device__ __align__(16) float g_y [MM*CC];        // attention output
__device__ __align__(16) float g_u1[MM*HFF_];      // mlp up 1 (silu-gated in place)
__device__ __align__(16) float g_u2[MM*HFF_];      // mlp up 2

// ---------------- input projection: h = x @ w_in^T  (K=9) ------------------
__global__ void k_input_proj(const float* __restrict__ x,
                             const float* __restrict__ w,
                             float* __restrict__ h) {
    int idx = blockIdx.x * blockDim.x + threadIdx.x;
    if (idx >= MM*CC) return;
    int m = idx >> 10;
    int c = idx & 1023;
    const float* xr = x + m*9;
    const float* wr = w + c*9;
    float s = 0.f;
    #pragma unroll
    for (int f = 0; f < 9; ++f) s += xr[f] * wr[f];
    h[idx] = s;
}

// ---------------- RMSNorm: out = in * rsqrt(mean(in^2)+eps) * g -------------
__global__ void k_rms(const float* __restrict__ in,
                      float* __restrict__ out,
                      const float* __restrict__ g) {
    int m = blockIdx.x;
    const float* r = in + (size_t)m * CC;
    float s = 0.f;
    for (int c = threadIdx.x; c < CC; c += 256) { float v = r[c]; s += v*v; }
    __shared__ float red[256];
    red[threadIdx.x] = s;
    __syncthreads();
    #pragma unroll
    for (int off = 128; off > 0; off >>= 1) {
        if (threadIdx.x < off) red[threadIdx.x] += red[threadIdx.x + off];
        __syncthreads();
    }
    float inv = rsqrtf(red[0] * (1.0f/CC) + 1e-5f);
    for (int c = threadIdx.x; c < CC; c += 256)
        out[(size_t)m*CC + c] = r[c] * inv * g[c];
}

// ---------------- tiled SGEMM: C[M,N] (+)= A[M,K] @ W[N,K]^T ----------------
// BM=BN=128, BK=16, 256 threads, 8x8 microtile. M,N multiples of 128; K of 16.
template<bool ADD>
__global__ void k_gemm(const float* __restrict__ A,
                       const float* __restrict__ W,
                       float* __restrict__ Cm,
                       int M, int N, int K) {
    const int BM = 128, BN = 128, BK = 16;
    __shared__ float As[BK][BM+4];
    __shared__ float Bs[BK][BN+4];
    int tid = threadIdx.x;
    int tx = tid & 15, ty = tid >> 4;
    int m0 = blockIdx.y * BM, n0 = blockIdx.x * BN;

    float acc[8][8];
    #pragma unroll
    for (int i = 0; i < 8; ++i)
        #pragma unroll
        for (int j = 0; j < 8; ++j) acc[i][j] = 0.f;

    for (int k0 = 0; k0 < K; k0 += BK) {
        #pragma unroll
        for (int it = 0; it < 2; ++it) {
            int id  = tid + it*256;           // 0..511
            int row = id >> 2;                // 0..127
            int k4  = (id & 3) * 4;           // 0,4,8,12
            float4 va = *(const float4*)(A + (size_t)(m0+row)*K + k0 + k4);
            As[k4+0][row] = va.x; As[k4+1][row] = va.y;
            As[k4+2][row] = va.z; As[k4+3][row] = va.w;
            float4 vb = *(const float4*)(W + (size_t)(n0+row)*K + k0 + k4);
            Bs[k4+0][row] = vb.x; Bs[k4+1][row] = vb.y;
            Bs[k4+2][row] = vb.z; Bs[k4+3][row] = vb.w;
        }
        __syncthreads();
        #pragma unroll
        for (int k = 0; k < BK; ++k) {
            float ar[8], br[8];
            *(float4*)&ar[0] = *(const float4*)&As[k][ty*8];
            *(float4*)&ar[4] = *(const float4*)&As[k][ty*8+4];
            *(float4*)&br[0] = *(const float4*)&Bs[k][tx*8];
            *(float4*)&br[4] = *(const float4*)&Bs[k][tx*8+4];
            #pragma unroll
            for (int i = 0; i < 8; ++i)
                #pragma unroll
                for (int j = 0; j < 8; ++j) acc[i][j] += ar[i]*br[j];
        }
        __syncthreads();
    }

    #pragma unroll
    for (int i = 0; i < 8; ++i) {
        float* cp = Cm + (size_t)(m0 + ty*8 + i)*N + n0 + tx*8;
        if (ADD) {
            #pragma unroll
            for (int j = 0; j < 8; ++j) cp[j] += acc[i][j];
        } else {
            *(float4*)&cp[0] = *(float4*)&acc[i][0];
            *(float4*)&cp[4] = *(float4*)&acc[i][4];
        }
    }
}

// ---------------- RoPE (in place on q and on k-half of kv) ------------------
__global__ void k_rope(float* __restrict__ q, float* __restrict__ kv) {
    int idx = blockIdx.x * blockDim.x + threadIdx.x;   // MM*CC/2 pairs
    if (idx >= MM*CC/2) return;
    int i    = idx & 31;          // 0..31 rotation pair index
    int head = (idx >> 5) & 15;
    int m    = idx >> 9;
    int t    = m & (TT - 1);
    float invf = powf(10000.0f, -(2.0f * i) / 64.0f);
    float ang  = (float)t * invf;
    float c = cosf(ang), s = sinf(ang);

    size_t qb = (size_t)m*CC + head*64 + i;
    float x1 = q[qb], x2 = q[qb+32];
    q[qb]    = x1*c - x2*s;
    q[qb+32] = x2*c + x1*s;

    size_t kb = (size_t)m*(2*CC) + head*64 + i;
    float y1 = kv[kb], y2 = kv[kb+32];
    kv[kb]    = y1*c - y2*s;
    kv[kb+32] = y2*c + y1*s;
}

// ---------------- flash attention: 64-query tile per CTA --------------------
// grid (T/64, NH, B), 256 threads, dynamic smem.
#define ATTN_P 68
#define ATTN_SMEM ((4*64*ATTN_P + 3*64) * (int)sizeof(float))   // 70400 B
__global__ void k_attn(const float* __restrict__ q,
                       const float* __restrict__ kv,
                       float* __restrict__ y) {
    extern __shared__ float sm[];
    const int P = ATTN_P;
    float* Qs   = sm;              // [64][P]
    float* KT   = Qs + 64*P;       // [d][s]
    float* Vs   = KT + 64*P;       // [s][d]
    float* Ss   = Vs + 64*P;       // [64][P]
    float* mrow = Ss + 64*P;
    float* lrow = mrow + 64;
    float* arow = lrow + 64;

    int tid  = threadIdx.x;
    int qt   = blockIdx.x, head = blockIdx.y, b = blockIdx.z;
    int r    = tid >> 2;           // query row 0..63
    int db   = (tid & 3) * 16;     // 16-wide chunk (dims or keys)

    #pragma unroll
    for (int i = 0; i < 16; ++i) {
        int e = tid + i*256;
        int rr = e >> 6, d = e & 63;
        Qs[rr*P + d] = q[(size_t)(b*TT + qt*64 + rr)*CC + head*64 + d] * 0.125f;
    }
    if (tid < 64) { mrow[tid] = -INFINITY; lrow[tid] = 0.f; }
    float o[16];
    #pragma unroll
    for (int j = 0; j < 16; ++j) o[j] = 0.f;

    for (int kt = 0; kt <= qt; ++kt) {
        __syncthreads();
        #pragma unroll
        for (int i = 0; i < 16; ++i) {
            int e = tid + i*256;
            int s = e >> 6, d = e & 63;
            size_t base = (size_t)(b*TT + kt*64 + s)*(2*CC) + head*64 + d;
            KT[d*P + s] = kv[base];
            Vs[s*P + d] = kv[base + CC];
        }
        __syncthreads();

        // S[r, db..db+15] = Q[r,:] . K[s,:]
        float accv[16];
        #pragma unroll
        for (int j = 0; j < 16; ++j) accv[j] = 0.f;
        #pragma unroll 8
        for (int d = 0; d < 64; ++d) {
            float qv = Qs[r*P + d];
            float kvv[16];
            *(float4*)&kvv[0]  = *(const float4*)&KT[d*P + db + 0];
            *(float4*)&kvv[4]  = *(const float4*)&KT[d*P + db + 4];
            *(float4*)&kvv[8]  = *(const float4*)&KT[d*P + db + 8];
            *(float4*)&kvv[12] = *(const float4*)&KT[d*P + db + 12];
            #pragma unroll
            for (int j = 0; j < 16; ++j) accv[j] += qv * kvv[j];
        }
        int rg = qt*64 + r;
        #pragma unroll
        for (int j = 0; j < 16; ++j) {
            int sc = kt*64 + db + j;
            Ss[r*P + db + j] = (sc > rg) ? -INFINITY : accv[j];
        }
        __syncthreads();

        // online softmax row pass (one thread per query row)
        if (tid < 64) {
            int rr = tid;
            float mt = -INFINITY;
            #pragma unroll 8
            for (int s = 0; s < 64; ++s) mt = fmaxf(mt, Ss[rr*P + s]);
            float mold = mrow[rr];
            float mnew = fmaxf(mold, mt);
            float a = expf(mold - mnew);
            float ls = 0.f;
            #pragma unroll 8
            for (int s = 0; s < 64; ++s) {
                float p = expf(Ss[rr*P + s] - mnew);
                Ss[rr*P + s] = p;
                ls += p;
            }
            lrow[rr] = lrow[rr]*a + ls;
            mrow[rr] = mnew;
            arow[rr] = a;
        }
        __syncthreads();

        // O[r, db..] = a*O + P[r,:] @ V[:, db..]
        float a = arow[r];
        #pragma unroll
        for (int j = 0; j < 16; ++j) o[j] *= a;
        #pragma unroll 8
        for (int s = 0; s < 64; ++s) {
            float p = Ss[r*P + s];
            float vv[16];
            *(float4*)&vv[0]  = *(const float4*)&Vs[s*P + db + 0];
            *(float4*)&vv[4]  = *(const float4*)&Vs[s*P + db + 4];
            *(float4*)&vv[8]  = *(const float4*)&Vs[s*P + db + 8];
            *(float4*)&vv[12] = *(const float4*)&Vs[s*P + db + 12];
            #pragma unroll
            for (int j = 0; j < 16; ++j) o[j] += p * vv[j];
        }
    }

    float invl = 1.f / lrow[r];
    float* yp = y + (size_t)(b*TT + qt*64 + r)*CC + head*64 + db;
    #pragma unroll
    for (int j = 0; j < 16; ++j) yp[j] = o[j] * invl;
}

// ---------------- SiLU gate: u1 = silu(u1) * u2 -----------------------------
__global__ void k_silu(float* __restrict__ u1, const float* __restrict__ u2) {
    int idx = blockIdx.x * blockDim.x + threadIdx.x;
    if (idx >= MM*HFF_) return;
    float v = u1[idx];
    float sig = 1.f / (1.f + expf(-v));
    u1[idx] = v * sig * u2[idx];
}

// ---------------- final RMSNorm directly into d_out -------------------------
__global__ void k_rms_out(const float* __restrict__ in,
                          float* __restrict__ out,
                          const float* __restrict__ g) {
    int m = blockIdx.x;
    const float* r = in + (size_t)m * CC;
    float s = 0.f;
    for (int c = threadIdx.x; c < CC; c += 256) { float v = r[c]; s += v*v; }
    __shared__ float red[256];
    red[threadIdx.x] = s;
    __syncthreads();
    #pragma unroll
    for (int off = 128; off > 0; off >>= 1) {
        if (threadIdx.x < off) red[threadIdx.x] += red[threadIdx.x + off];
        __syncthreads();
    }
    float inv = rsqrtf(red[0] * (1.0f/CC) + 1e-5f);
    for (int c = threadIdx.x; c < CC; c += 256)
        out[(size_t)m*CC + c] = r[c] * inv * g[c];
}

// ---------------- orchestration --------------------------------------------
extern "C" void kernel_launch(void* const* d_in, const int* in_sizes, int n_in,
                              void* d_out, int out_size) {
    const float* x    = (const float*)d_in[0];
    const float* w_in = (const float*)d_in[1];
    const float* wq   = (const float*)d_in[2];
    const float* wkv  = (const float*)d_in[3];
    const float* wo   = (const float*)d_in[4];
    const float* w1   = (const float*)d_in[5];
    const float* w2   = (const float*)d_in[6];
    const float* w3   = (const float*)d_in[7];
    const float* g1   = (const float*)d_in[8];
    const float* g2   = (const float*)d_in[9];
    const float* gf   = (const float*)d_in[10];
    float* out = (float*)d_out;

    float *h, *a, *q, *kv, *y, *u1, *u2;
    cudaGetSymbolAddress((void**)&h,  g_h);
    cudaGetSymbolAddress((void**)&a,  g_a);
    cudaGetSymbolAddress((void**)&q,  g_q);
    cudaGetSymbolAddress((void**)&kv, g_kv);
    cudaGetSymbolAddress((void**)&y,  g_y);
    cudaGetSymbolAddress((void**)&u1, g_u1);
    cudaGetSymbolAddress((void**)&u2, g_u2);

    cudaFuncSetAttribute(k_attn, cudaFuncAttributeMaxDynamicSharedMemorySize,
                         ATTN_SMEM);

    k_input_proj<<<MM*CC/256, 256>>>(x, w_in, h);

    for (int l = 0; l < LLAYERS; ++l) {
        const float* wq_l  = wq  + (size_t)l*CC*CC;
        const float* wkv_l = wkv + (size_t)l*2*CC*CC;
        const float* wo_l  = wo  + (size_t)l*CC*CC;
        const float* w1_l  = w1  + (size_t)l*HFF_*CC;
        const float* w2_l  = w2  + (size_t)l*HFF_*CC;
        const float* w3_l  = w3  + (size_t)l*CC*HFF_;

        // --- attention block ---
        k_rms<<<MM, 256>>>(h, a, g1 + l*CC);
        k_gemm<false><<<dim3(CC/128,   MM/128), 256>>>(a, wq_l,  q,  MM, CC,   CC);
        k_gemm<false><<<dim3(2*CC/128, MM/128), 256>>>(a, wkv_l, kv, MM, 2*CC, CC);
        k_rope<<<(MM*CC/2)/256, 256>>>(q, kv);
        k_attn<<<dim3(TT/64, NHH, BB), 256, ATTN_SMEM>>>(q, kv, y);
        k_gemm<true><<<dim3(CC/128, MM/128), 256>>>(y, wo_l, h, MM, CC, CC);

        // --- MLP block ---
        k_rms<<<MM, 256>>>(h, a, g2 + l*CC);
        k_gemm<false><<<dim3(HFF_/128, MM/128), 256>>>(a, w1_l, u1, MM, HFF_, CC);
        k_gemm<false><<<dim3(HFF_/128, MM/128), 256>>>(a, w2_l, u2, MM, HFF_, CC);
        k_silu<<<(MM*HFF_)/256, 256>>>(u1, u2);
        k_gemm<true><<<dim3(CC/128, MM/128), 256>>>(u1, w3_l, h, MM, CC, HFF_);
    }

    k_rms_out<<<MM, 256>>>(h, out, gf);
}

// round 2
// speedup vs baseline: 1.2685x; 1.2685x over previous
#include <cuda_runtime.h>
#include <cuda_fp16.h>
#include <math.h>

#define BB   2
#define TT   1024
#define CC   1024
#define NHH  16
#define DHH  64
#define LLAYERS 4
#define HFF_ 2816
#define MM   (BB*TT)          // 2048 rows

// ---------------- scratch (static device globals; no allocation allowed) ---
__device__ __align__(16) float g_h   [MM*CC];          // residual stream (fp32)
__device__ __align__(16) __half g_a2 [MM*2*CC];        // rms-normed acts, [hi|lo]
__device__ __align__(16) float g_qkv [MM*3*CC];        // fused q|k|v projection (fp32)
__device__ __align__(16) __half g_y2 [MM*2*CC];        // attention out, [hi|lo]
__device__ __align__(16) float g_u1  [MM*HFF_];        // mlp up 1 (fp32)
__device__ __align__(16) float g_u2  [MM*HFF_];        // mlp up 2 (fp32)
__device__ __align__(16) __half g_u12[MM*2*HFF_];      // gated, [hi|lo]

// split fp16 weights, row layout [row][hi(K) | lo(K)]
__device__ __align__(16) __half g_wqkv2[LLAYERS*3*CC*2*CC];
__device__ __align__(16) __half g_wo2  [LLAYERS*CC*2*CC];
__device__ __align__(16) __half g_w12  [LLAYERS*HFF_*2*CC];
__device__ __align__(16) __half g_w22  [LLAYERS*HFF_*2*CC];
__device__ __align__(16) __half g_w32  [LLAYERS*CC*2*HFF_];

// ---------------- weight split conversion ----------------------------------
__global__ void k_split_w(const float* __restrict__ src, __half* __restrict__ dst,
                          int total, int K) {
    int idx = blockIdx.x * blockDim.x + threadIdx.x;
    if (idx >= total) return;
    int r = idx / K;
    int k = idx - r * K;
    float v = src[idx];
    __half hi = __float2half(v);
    __half lo = __float2half(v - __half2float(hi));
    dst[(size_t)r*2*K + k]     = hi;
    dst[(size_t)r*2*K + K + k] = lo;
}

__global__ void k_split_qkv_w(const float* __restrict__ wq,
                              const float* __restrict__ wkv,
                              __half* __restrict__ dst) {
    int idx = blockIdx.x * blockDim.x + threadIdx.x;   // L*3072*1024 total
    if (idx >= LLAYERS*3*CC*CC) return;
    int l   = idx / (3*CC*CC);
    int rem = idx - l*(3*CC*CC);
    int row = rem >> 10;
    int k   = rem & 1023;
    float v = (row < CC)
        ? wq [((size_t)l*CC   + row)      * CC + k]
        : wkv[((size_t)l*2*CC + (row-CC)) * CC + k];
    __half hi = __float2half(v);
    __half lo = __float2half(v - __half2float(hi));
    __half* d = dst + ((size_t)l*3*CC + row)*2*CC;
    d[k]      = hi;
    d[CC + k] = lo;
}

// ---------------- input projection: h = x @ w_in^T  (K=9) ------------------
__global__ void k_input_proj(const float* __restrict__ x,
                             const float* __restrict__ w,
                             float* __restrict__ h) {
    int idx = blockIdx.x * blockDim.x + threadIdx.x;
    if (idx >= MM*CC) return;
    int m = idx >> 10;
    int c = idx & 1023;
    const float* xr = x + m*9;
    const float* wr = w + c*9;
    float s = 0.f;
    #pragma unroll
    for (int f = 0; f < 9; ++f) s += xr[f] * wr[f];
    h[idx] = s;
}

// ---------------- RMSNorm -> split fp16 hi/lo -------------------------------
__global__ void k_rms_h(const float* __restrict__ in,
                        __half* __restrict__ out2,     // [M][2C]
                        const float* __restrict__ g) {
    int m = blockIdx.x;
    const float* r = in + (size_t)m * CC;
    float s = 0.f;
    for (int c = threadIdx.x; c < CC; c += 256) { float v = r[c]; s += v*v; }
    __shared__ float red[256];
    red[threadIdx.x] = s;
    __syncthreads();
    #pragma unroll
    for (int off = 128; off > 0; off >>= 1) {
        if (threadIdx.x < off) red[threadIdx.x] += red[threadIdx.x + off];
        __syncthreads();
    }
    float inv = rsqrtf(red[0] * (1.0f/CC) + 1e-5f);
    for (int c = threadIdx.x; c < CC; c += 256) {
        float v = r[c] * inv * g[c];
        __half hi = __float2half(v);
        out2[(size_t)m*2*CC + c]      = hi;
        out2[(size_t)m*2*CC + CC + c] = __float2half(v - __half2float(hi));
    }
}

// ---------------- fp16x3 tensor-core GEMM ----------------------------------
// C[M,N] (+)= A[M,K]*W[N,K]^T computed as Ahi*Whi + Alo*Whi + Ahi*Wlo.
// A,W stored as [row][hi(K)|lo(K)] fp16. BM=128, BN in {128,64}, BK=32.
// 256 threads = 8 warps: warp grid 4(m) x 2(n); warp tile 32 x (BN/2).
__device__ __forceinline__ void mma16816(float* d, const unsigned* a, const unsigned* b) {
    asm volatile(
        "mma.sync.aligned.m16n8k16.row.col.f32.f16.f16.f32 "
        "{%0,%1,%2,%3}, {%4,%5,%6,%7}, {%8,%9}, {%0,%1,%2,%3};\n"
        : "+f"(d[0]), "+f"(d[1]), "+f"(d[2]), "+f"(d[3])
        : "r"(a[0]), "r"(a[1]), "r"(a[2]), "r"(a[3]), "r"(b[0]), "r"(b[1]));
}

template<int BN, bool ADD>
__global__ void k_hgemm(const __half* __restrict__ A,   // [M][2K]
                        const __half* __restrict__ W,   // [N][2K]
                        float* __restrict__ C,          // [M][N]
                        int M, int N, int K) {
    constexpr int NT = BN / 16;        // n-tiles (of 8) per warp
    __shared__ __half As[128][40];
    __shared__ __half Ws[BN][40];

    int tid  = threadIdx.x;
    int wid  = tid >> 5, lane = tid & 31;
    int wm   = wid & 3,  wn   = wid >> 2;
    int g    = lane >> 2, t   = lane & 3;
    int m0   = blockIdx.y * 128, n0 = blockIdx.x * BN;
    int ld   = 2 * K;
    int lrow = tid >> 2;               // 0..63
    int lk   = (tid & 3) * 8;          // 0,8,16,24

    float acc[2][NT][4];
    #pragma unroll
    for (int mi = 0; mi < 2; ++mi)
        #pragma unroll
        for (int ni = 0; ni < NT; ++ni)
            #pragma unroll
            for (int q = 0; q < 4; ++q) acc[mi][ni][q] = 0.f;

    #pragma unroll 1
    for (int seg = 0; seg < 3; ++seg) {
        const __half* Ag = A + (seg == 1 ? K : 0);
        const __half* Wg = W + (seg == 2 ? K : 0);
        #pragma unroll 1
        for (int k0 = 0; k0 < K; k0 += 32) {
            *(uint4*)&As[lrow][lk] =
                *(const uint4*)&Ag[(size_t)(m0 + lrow)*ld + k0 + lk];
            *(uint4*)&As[lrow + 64][lk] =
                *(const uint4*)&Ag[(size_t)(m0 + lrow + 64)*ld + k0 + lk];
            *(uint4*)&Ws[lrow][lk] =
                *(const uint4*)&Wg[(size_t)(n0 + lrow)*ld + k0 + lk];
            if (BN == 128)
                *(uint4*)&Ws[lrow + 64][lk] =
                    *(const uint4*)&Wg[(size_t)(n0 + lrow + 64)*ld + k0 + lk];
            __syncthreads();

            #pragma unroll
            for (int kk = 0; kk < 32; kk += 16) {
                unsigned af[2][4], bf[NT][2];
                #pragma unroll
                for (int mi = 0; mi < 2; ++mi) {
                    int mb = wm*32 + mi*16;
                    af[mi][0] = *(const unsigned*)&As[mb + g    ][kk + 2*t];
                    af[mi][1] = *(const unsigned*)&As[mb + g + 8][kk + 2*t];
                    af[mi][2] = *(const unsigned*)&As[mb + g    ][kk + 2*t + 8];
                    af[mi][3] = *(const unsigned*)&As[mb + g + 8][kk + 2*t + 8];
                }
                #pragma unroll
                for (int ni = 0; ni < NT; ++ni) {
                    int nb = wn*(NT*8) + ni*8;
                    bf[ni][0] = *(const unsigned*)&Ws[nb + g][kk + 2*t];
                    bf[ni][1] = *(const unsigned*)&Ws[nb + g][kk + 2*t + 8];
                }
                #pragma unroll
                for (int mi = 0; mi < 2; ++mi)
                    #pragma unroll
                    for (int ni = 0; ni < NT; ++ni)
                        mma16816(acc[mi][ni], af[mi], bf[ni]);
            }
            __syncthreads();
        }
    }

    #pragma unroll
    for (int mi = 0; mi < 2; ++mi)
        #pragma unroll
        for (int ni = 0; ni < NT; ++ni) {
            int row = m0 + wm*32 + mi*16 + g;
            int col = n0 + wn*(NT*8) + ni*8 + 2*t;
            float2* p0 = (float2*)&C[(size_t)row*N + col];
            float2* p1 = (float2*)&C[(size_t)(row + 8)*N + col];
            if (ADD) {
                float2 v0 = *p0, v1 = *p1;
                v0.x += acc[mi][ni][0]; v0.y += acc[mi][ni][1];
                v1.x += acc[mi][ni][2]; v1.y += acc[mi][ni][3];
                *p0 = v0; *p1 = v1;
            } else {
                *p0 = make_float2(acc[mi][ni][0], acc[mi][ni][1]);
                *p1 = make_float2(acc[mi][ni][2], acc[mi][ni][3]);
            }
        }
}

// ---------------- RoPE (in place on q and k slices of qkv) ------------------
__global__ void k_rope(float* __restrict__ qkv) {
    int idx = blockIdx.x * blockDim.x + threadIdx.x;   // MM*512 pairs
    if (idx >= MM*512) return;
    int i    = idx & 31;          // rotation pair index
    int head = (idx >> 5) & 15;
    int m    = idx >> 9;
    int t    = m & (TT - 1);
    float invf = powf(10000.0f, -(2.0f * i) / 64.0f);
    float ang  = (float)t * invf;
    float c = cosf(ang), s = sinf(ang);

    size_t base = (size_t)m*(3*CC) + head*64 + i;
    float x1 = qkv[base], x2 = qkv[base+32];
    qkv[base]      = x1*c - x2*s;
    qkv[base+32]   = x2*c + x1*s;

    size_t kb = base + CC;
    float y1 = qkv[kb], y2 = qkv[kb+32];
    qkv[kb]    = y1*c - y2*s;
    qkv[kb+32] = y2*c + y1*s;
}

// ---------------- flash attention: 64-query tile per CTA --------------------
// grid (T/64, NH, B), 256 threads, dynamic smem. Writes split fp16 y.
#define ATTN_P 68
#define ATTN_SMEM ((4*64*ATTN_P + 2*64) * (int)sizeof(float))
__global__ void k_attn(const float* __restrict__ qkv,
                       __half* __restrict__ y2) {
    extern __shared__ float sm[];
    const int P = ATTN_P;
    float* Qs   = sm;              // [64][P]
    float* KT   = Qs + 64*P;       // [d][s]
    float* Vs   = KT + 64*P;       // [s][d]
    float* Ss   = Vs + 64*P;       // [64][P]
    float* mrow = Ss + 64*P;
    float* lrow = mrow + 64;

    int tid  = threadIdx.x;
    int qt   = blockIdx.x, head = blockIdx.y, b = blockIdx.z;
    int r    = tid >> 2;           // query row 0..63
    int db   = (tid & 3) * 16;     // 16-wide key/dim chunk

    #pragma unroll
    for (int i = 0; i < 16; ++i) {
        int e = tid + i*256;
        int rr = e >> 6, d = e & 63;
        Qs[rr*P + d] = qkv[(size_t)(b*TT + qt*64 + rr)*(3*CC) + head*64 + d] * 0.125f;
    }
    if (tid < 64) { mrow[tid] = -INFINITY; lrow[tid] = 0.f; }
    float o[16];
    #pragma unroll
    for (int j = 0; j < 16; ++j) o[j] = 0.f;

    for (int kt = 0; kt <= qt; ++kt) {
        __syncthreads();
        #pragma unroll
        for (int i = 0; i < 16; ++i) {
            int e = tid + i*256;
            int s = e >> 6, d = e & 63;
            size_t base = (size_t)(b*TT + kt*64 + s)*(3*CC) + CC + head*64 + d;
            KT[d*P + s] = qkv[base];
            Vs[s*P + d] = qkv[base + CC];
        }
        __syncthreads();

        // S[r, db..db+15]
        float accv[16];
        #pragma unroll
        for (int j = 0; j < 16; ++j) accv[j] = 0.f;
        #pragma unroll 8
        for (int d = 0; d < 64; ++d) {
            float qv = Qs[r*P + d];
            float kvv[16];
            *(float4*)&kvv[0]  = *(const float4*)&KT[d*P + db + 0];
            *(float4*)&kvv[4]  = *(const float4*)&KT[d*P + db + 4];
            *(float4*)&kvv[8]  = *(const float4*)&KT[d*P + db + 8];
            *(float4*)&kvv[12] = *(const float4*)&KT[d*P + db + 12];
            #pragma unroll
            for (int j = 0; j < 16; ++j) accv[j] += qv * kvv[j];
        }
        int rg = qt*64 + r;
        #pragma unroll
        for (int j = 0; j < 16; ++j)
            if (kt*64 + db + j > rg) accv[j] = -INFINITY;

        // register-resident online softmax (quad reduce across the 4 chunk threads)
        float lm = -INFINITY;
        #pragma unroll
        for (int j = 0; j < 16; ++j) lm = fmaxf(lm, accv[j]);
        lm = fmaxf(lm, __shfl_xor_sync(0xffffffffu, lm, 1));
        lm = fmaxf(lm, __shfl_xor_sync(0xffffffffu, lm, 2));
        float mold = mrow[r];
        float mnew = fmaxf(mold, lm);
        float a = __expf(mold - mnew);
        float ls = 0.f;
        #pragma unroll
        for (int j = 0; j < 16; ++j) {
            float p = __expf(accv[j] - mnew);
            Ss[r*P + db + j] = p;
            ls += p;
        }
        ls += __shfl_xor_sync(0xffffffffu, ls, 1);
        ls += __shfl_xor_sync(0xffffffffu, ls, 2);
        __syncwarp();
        if ((tid & 3) == 0) {
            lrow[r] = lrow[r]*a + ls;
            mrow[r] = mnew;
        }
        #pragma unroll
        for (int j = 0; j < 16; ++j) o[j] *= a;
        __syncthreads();

        // O[r, db..] += P[r,:] @ V[:, db..]
        #pragma unroll 8
        for (int s = 0; s < 64; ++s) {
            float p = Ss[r*P + s];
            float vv[16];
            *(float4*)&vv[0]  = *(const float4*)&Vs[s*P + db + 0];
            *(float4*)&vv[4]  = *(const float4*)&Vs[s*P + db + 4];
            *(float4*)&vv[8]  = *(const float4*)&Vs[s*P + db + 8];
            *(float4*)&vv[12] = *(const float4*)&Vs[s*P + db + 12];
            #pragma unroll
            for (int j = 0; j < 16; ++j) o[j] += p * vv[j];
        }
    }

    float invl = 1.f / lrow[r];
    size_t yb = (size_t)(b*TT + qt*64 + r)*(2*CC) + head*64 + db;
    #pragma unroll
    for (int j = 0; j < 16; ++j) {
        float v = o[j] * invl;
        __half hi = __float2half(v);
        y2[yb + j]      = hi;
        y2[yb + CC + j] = __float2half(v - __half2float(hi));
    }
}

// ---------------- SiLU gate -> split fp16 -----------------------------------
__global__ void k_silu_h(const float* __restrict__ u1,
                         const float* __restrict__ u2,
                         __half* __restrict__ u12) {   // [M][2*HFF]
    int idx = blockIdx.x * blockDim.x + threadIdx.x;
    if (idx >= MM*HFF_) return;
    int m = idx / HFF_;
    int c = idx - m*HFF_;
    float v = u1[idx];
    float sig = 1.f / (1.f + __expf(-v));
    float gval = v * sig * u2[idx];
    __half hi = __float2half(gval);
    u12[(size_t)m*2*HFF_ + c]        = hi;
    u12[(size_t)m*2*HFF_ + HFF_ + c] = __float2half(gval - __half2float(hi));
}

// ---------------- final RMSNorm into d_out ----------------------------------
__global__ void k_rms_out(const float* __restrict__ in,
                          float* __restrict__ out,
                          const float* __restrict__ g) {
    int m = blockIdx.x;
    const float* r = in + (size_t)m * CC;
    float s = 0.f;
    for (int c = threadIdx.x; c < CC; c += 256) { float v = r[c]; s += v*v; }
    __shared__ float red[256];
    red[threadIdx.x] = s;
    __syncthreads();
    #pragma unroll
    for (int off = 128; off > 0; off >>= 1) {
        if (threadIdx.x < off) red[threadIdx.x] += red[threadIdx.x + off];
        __syncthreads();
    }
    float inv = rsqrtf(red[0] * (1.0f/CC) + 1e-5f);
    for (int c = threadIdx.x; c < CC; c += 256)
        out[(size_t)m*CC + c] = r[c] * inv * g[c];
}

// ---------------- orchestration --------------------------------------------
extern "C" void kernel_launch(void* const* d_in, const int* in_sizes, int n_in,
                              void* d_out, int out_size) {
    const float* x    = (const float*)d_in[0];
    const float* w_in = (const float*)d_in[1];
    const float* wq   = (const float*)d_in[2];
    const float* wkv  = (const float*)d_in[3];
    const float* wo   = (const float*)d_in[4];
    const float* w1   = (const float*)d_in[5];
    const float* w2   = (const float*)d_in[6];
    const float* w3   = (const float*)d_in[7];
    const float* g1   = (const float*)d_in[8];
    const float* g2   = (const float*)d_in[9];
    const float* gf   = (const float*)d_in[10];
    float* out = (float*)d_out;

    float *h, *qkvb, *u1, *u2;
    __half *a2, *y2, *u12, *wqkv2, *wo2, *w12, *w22, *w32;
    cudaGetSymbolAddress((void**)&h,    g_h);
    cudaGetSymbolAddress((void**)&a2,   g_a2);
    cudaGetSymbolAddress((void**)&qkvb, g_qkv);
    cudaGetSymbolAddress((void**)&y2,   g_y2);
    cudaGetSymbolAddress((void**)&u1,   g_u1);
    cudaGetSymbolAddress((void**)&u2,   g_u2);
    cudaGetSymbolAddress((void**)&u12,  g_u12);
    cudaGetSymbolAddress((void**)&wqkv2,g_wqkv2);
    cudaGetSymbolAddress((void**)&wo2,  g_wo2);
    cudaGetSymbolAddress((void**)&w12,  g_w12);
    cudaGetSymbolAddress((void**)&w22,  g_w22);
    cudaGetSymbolAddress((void**)&w32,  g_w32);

    cudaFuncSetAttribute(k_attn, cudaFuncAttributeMaxDynamicSharedMemorySize,
                         ATTN_SMEM);

    // weight splits (every launch; ~70us of HBM traffic)
    {
        int n;
        n = LLAYERS*3*CC*CC;
        k_split_qkv_w<<<(n+255)/256, 256>>>(wq, wkv, wqkv2);
        n = LLAYERS*CC*CC;
        k_split_w<<<(n+255)/256, 256>>>(wo, wo2, n, CC);
        n = LLAYERS*HFF_*CC;
        k_split_w<<<(n+255)/256, 256>>>(w1, w12, n, CC);
        k_split_w<<<(n+255)/256, 256>>>(w2, w22, n, CC);
        n = LLAYERS*CC*HFF_;
        k_split_w<<<(n+255)/256, 256>>>(w3, w32, n, HFF_);
    }

    k_input_proj<<<MM*CC/256, 256>>>(x, w_in, h);

    for (int l = 0; l < LLAYERS; ++l) {
        const __half* wqkv_l = wqkv2 + (size_t)l*3*CC*2*CC;
        const __half* wo_l   = wo2   + (size_t)l*CC*2*CC;
        const __half* w1_l   = w12   + (size_t)l*HFF_*2*CC;
        const __half* w2_l   = w22   + (size_t)l*HFF_*2*CC;
        const __half* w3_l   = w32   + (size_t)l*CC*2*HFF_;

        // --- attention block ---
        k_rms_h<<<MM, 256>>>(h, a2, g1 + l*CC);
        k_hgemm<128,false><<<dim3(3*CC/128, MM/128), 256>>>(a2, wqkv_l, qkvb, MM, 3*CC, CC);
        k_rope<<<(MM*512)/256, 256>>>(qkvb);
        k_attn<<<dim3(TT/64, NHH, BB), 256, ATTN_SMEM>>>(qkvb, y2);
        k_hgemm<64,true><<<dim3(CC/64, MM/128), 256>>>(y2, wo_l, h, MM, CC, CC);

        // --- MLP block ---
        k_rms_h<<<MM, 256>>>(h, a2, g2 + l*CC);
        k_hgemm<128,false><<<dim3(HFF_/128, MM/128), 256>>>(a2, w1_l, u1, MM, HFF_, CC);
        k_hgemm<128,false><<<dim3(HFF_/128, MM/128), 256>>>(a2, w2_l, u2, MM, HFF_, CC);
        k_silu_h<<<(MM*HFF_+255)/256, 256>>>(u1, u2, u12);
        k_hgemm<64,true><<<dim3(CC/64, MM/128), 256>>>(u12, w3_l, h, MM, CC, HFF_);
    }

    k_rms_out<<<MM, 256>>>(h, out, gf);
}

// round 3
// speedup vs baseline: 2.4871x; 1.9607x over previous
#include <cuda_runtime.h>
#include <cuda_fp16.h>
#include <math.h>

#define BB   2
#define TT   1024
#define CC   1024
#define NHH  16
#define DHH  64
#define LLAYERS 4
#define HFF_ 2816
#define MM   (BB*TT)          // 2048 rows

// ---------------- scratch (static device globals) ---------------------------
__device__ __align__(16) float  g_h   [MM*CC];
__device__ __align__(16) __half g_a2  [MM*2*CC];     // rms acts [hi|lo]
__device__ __align__(16) float  g_qkv [MM*3*CC];     // fused q|k|v (fp32)
__device__ __align__(16) __half g_qh  [MM*CC];       // roped q hi (pre-scaled)
__device__ __align__(16) __half g_ql  [MM*CC];
__device__ __align__(16) __half g_kh  [MM*CC];
__device__ __align__(16) __half g_kl  [MM*CC];
__device__ __align__(16) __half g_vth [MM*CC];       // V^T [b][h][d][t] hi
__device__ __align__(16) __half g_vtl [MM*CC];
__device__ __align__(16) __half g_y2  [MM*2*CC];     // attn out [hi|lo]
__device__ __align__(16) float  g_u1  [MM*HFF_];
__device__ __align__(16) float  g_u2  [MM*HFF_];
__device__ __align__(16) __half g_u12 [MM*2*HFF_];

// split fp16 weights, row layout [row][hi(K) | lo(K)]
__device__ __align__(16) __half g_wqkv2[LLAYERS*3*CC*2*CC];
__device__ __align__(16) __half g_wo2  [LLAYERS*CC*2*CC];
__device__ __align__(16) __half g_w12  [LLAYERS*HFF_*2*CC];
__device__ __align__(16) __half g_w22  [LLAYERS*HFF_*2*CC];
__device__ __align__(16) __half g_w32  [LLAYERS*CC*2*HFF_];

// ---------------- async copy helpers ----------------------------------------
__device__ __forceinline__ void cp16(void* smem_dst, const void* gsrc) {
    unsigned d = (unsigned)__cvta_generic_to_shared(smem_dst);
    asm volatile("cp.async.ca.shared.global [%0], [%1], 16;\n" :: "r"(d), "l"(gsrc));
}
#define CP_COMMIT()  asm volatile("cp.async.commit_group;\n")
#define CP_WAIT(N)   asm volatile("cp.async.wait_group %0;\n" :: "n"(N))

__device__ __forceinline__ void mma16816(float* d, const unsigned* a, const unsigned* b) {
    asm volatile(
        "mma.sync.aligned.m16n8k16.row.col.f32.f16.f16.f32 "
        "{%0,%1,%2,%3}, {%4,%5,%6,%7}, {%8,%9}, {%0,%1,%2,%3};\n"
        : "+f"(d[0]), "+f"(d[1]), "+f"(d[2]), "+f"(d[3])
        : "r"(a[0]), "r"(a[1]), "r"(a[2]), "r"(a[3]), "r"(b[0]), "r"(b[1]));
}

// pack two floats into half2 hi + half2 lo (residual)
__device__ __forceinline__ void pack2(float x, float y, unsigned& hi, unsigned& lo) {
    __half hx = __float2half(x), hy = __float2half(y);
    __half lx = __float2half(x - __half2float(hx));
    __half ly = __float2half(y - __half2float(hy));
    hi = (unsigned)__half_as_ushort(hx) | ((unsigned)__half_as_ushort(hy) << 16);
    lo = (unsigned)__half_as_ushort(lx) | ((unsigned)__half_as_ushort(ly) << 16);
}

// ---------------- weight split conversion ------------------------------------
__global__ void k_split_w(const float* __restrict__ src, __half* __restrict__ dst,
                          int total, int K) {
    int idx = blockIdx.x * blockDim.x + threadIdx.x;
    if (idx >= total) return;
    int r = idx / K;
    int k = idx - r * K;
    float v = src[idx];
    __half hi = __float2half(v);
    __half lo = __float2half(v - __half2float(hi));
    dst[(size_t)r*2*K + k]     = hi;
    dst[(size_t)r*2*K + K + k] = lo;
}

__global__ void k_split_qkv_w(const float* __restrict__ wq,
                              const float* __restrict__ wkv,
                              __half* __restrict__ dst) {
    int idx = blockIdx.x * blockDim.x + threadIdx.x;
    if (idx >= LLAYERS*3*CC*CC) return;
    int l   = idx / (3*CC*CC);
    int rem = idx - l*(3*CC*CC);
    int row = rem >> 10;
    int k   = rem & 1023;
    float v = (row < CC)
        ? wq [((size_t)l*CC   + row)      * CC + k]
        : wkv[((size_t)l*2*CC + (row-CC)) * CC + k];
    __half hi = __float2half(v);
    __half lo = __float2half(v - __half2float(hi));
    __half* d = dst + ((size_t)l*3*CC + row)*2*CC;
    d[k]      = hi;
    d[CC + k] = lo;
}

// ---------------- input projection: h = x @ w_in^T  (K=9) --------------------
__global__ void k_input_proj(const float* __restrict__ x,
                             const float* __restrict__ w,
                             float* __restrict__ h) {
    int idx = blockIdx.x * blockDim.x + threadIdx.x;
    if (idx >= MM*CC) return;
    int m = idx >> 10;
    int c = idx & 1023;
    const float* xr = x + m*9;
    const float* wr = w + c*9;
    float s = 0.f;
    #pragma unroll
    for (int f = 0; f < 9; ++f) s += xr[f] * wr[f];
    h[idx] = s;
}

// ---------------- RMSNorm -> split fp16 hi/lo --------------------------------
__global__ void k_rms_h(const float* __restrict__ in,
                        __half* __restrict__ out2,     // [M][2C]
                        const float* __restrict__ g) {
    int m = blockIdx.x;
    const float* r = in + (size_t)m * CC;
    float s = 0.f;
    for (int c = threadIdx.x; c < CC; c += 256) { float v = r[c]; s += v*v; }
    __shared__ float red[256];
    red[threadIdx.x] = s;
    __syncthreads();
    #pragma unroll
    for (int off = 128; off > 0; off >>= 1) {
        if (threadIdx.x < off) red[threadIdx.x] += red[threadIdx.x + off];
        __syncthreads();
    }
    float inv = rsqrtf(red[0] * (1.0f/CC) + 1e-5f);
    for (int c = threadIdx.x; c < CC; c += 256) {
        float v = r[c] * inv * g[c];
        __half hi = __float2half(v);
        out2[(size_t)m*2*CC + c]      = hi;
        out2[(size_t)m*2*CC + CC + c] = __float2half(v - __half2float(hi));
    }
}

// ---------------- pipelined fp16x3 tensor-core GEMM --------------------------
// C[M,N] (+)= A[M,K]*W[N,K]^T as Ahi*Whi + Alo*Whi + Ahi*Wlo, single K pass.
// A,W stored [row][hi(K)|lo(K)]. BM=128, BN in {128,64}, BK=32, cp.async 2-stage.
template<int BN, bool ADD>
__global__ void k_hgemm(const __half* __restrict__ A,
                        const __half* __restrict__ W,
                        float* __restrict__ C,
                        int M, int N, int K) {
    constexpr int NT = BN / 16;                 // n-tiles(8) per warp
    constexpr int STAGE = (2*128 + 2*BN) * 40;  // halves per stage
    extern __shared__ __half sh[];

    int tid  = threadIdx.x;
    int wid  = tid >> 5, lane = tid & 31;
    int wm   = wid & 3,  wn   = wid >> 2;
    int g    = lane >> 2, t   = lane & 3;
    int m0   = blockIdx.y * 128, n0 = blockIdx.x * BN;
    int ld   = 2 * K;
    const __half* Abase = A + (size_t)m0 * ld;
    const __half* Wbase = W + (size_t)n0 * ld;

    float acc[2][NT][4];
    #pragma unroll
    for (int mi = 0; mi < 2; ++mi)
        #pragma unroll
        for (int ni = 0; ni < NT; ++ni)
            #pragma unroll
            for (int q = 0; q < 4; ++q) acc[mi][ni][q] = 0.f;

    auto load_stage = [&](int st, int k0) {
        __half* Ah = sh + st*STAGE;
        __half* Al = Ah + 128*40;
        __half* Wh = Al + 128*40;
        __half* Wl = Wh + BN*40;
        #pragma unroll
        for (int i = 0; i < 2; ++i) {
            int cid = tid*2 + i;            // 0..511
            int row = cid >> 2, kc = (cid & 3) * 8;
            const __half* s0 = Abase + (size_t)row*ld + k0 + kc;
            cp16(Ah + row*40 + kc, s0);
            cp16(Al + row*40 + kc, s0 + K);
        }
        if (BN == 128) {
            #pragma unroll
            for (int i = 0; i < 2; ++i) {
                int cid = tid*2 + i;
                int row = cid >> 2, kc = (cid & 3) * 8;
                const __half* s0 = Wbase + (size_t)row*ld + k0 + kc;
                cp16(Wh + row*40 + kc, s0);
                cp16(Wl + row*40 + kc, s0 + K);
            }
        } else {
            int row = tid >> 2, kc = (tid & 3) * 8;   // 64 rows x 4 chunks
            const __half* s0 = Wbase + (size_t)row*ld + k0 + kc;
            cp16(Wh + row*40 + kc, s0);
            cp16(Wl + row*40 + kc, s0 + K);
        }
    };

    auto compute_stage = [&](int st) {
        __half* Ah = sh + st*STAGE;
        __half* Al = Ah + 128*40;
        __half* Wh = Al + 128*40;
        __half* Wl = Wh + BN*40;
        #pragma unroll
        for (int kk = 0; kk < 32; kk += 16) {
            unsigned aH[2][4], aL[2][4];
            #pragma unroll
            for (int mi = 0; mi < 2; ++mi) {
                int mb = wm*32 + mi*16;
                aH[mi][0] = *(const unsigned*)&Ah[(mb+g  )*40 + kk + 2*t];
                aH[mi][1] = *(const unsigned*)&Ah[(mb+g+8)*40 + kk + 2*t];
                aH[mi][2] = *(const unsigned*)&Ah[(mb+g  )*40 + kk + 2*t + 8];
                aH[mi][3] = *(const unsigned*)&Ah[(mb+g+8)*40 + kk + 2*t + 8];
                aL[mi][0] = *(const unsigned*)&Al[(mb+g  )*40 + kk + 2*t];
                aL[mi][1] = *(const unsigned*)&Al[(mb+g+8)*40 + kk + 2*t];
                aL[mi][2] = *(const unsigned*)&Al[(mb+g  )*40 + kk + 2*t + 8];
                aL[mi][3] = *(const unsigned*)&Al[(mb+g+8)*40 + kk + 2*t + 8];
            }
            #pragma unroll
            for (int ni = 0; ni < NT; ++ni) {
                int nb = wn*(NT*8) + ni*8;
                unsigned bh[2], bl[2];
                bh[0] = *(const unsigned*)&Wh[(nb+g)*40 + kk + 2*t];
                bh[1] = *(const unsigned*)&Wh[(nb+g)*40 + kk + 2*t + 8];
                bl[0] = *(const unsigned*)&Wl[(nb+g)*40 + kk + 2*t];
                bl[1] = *(const unsigned*)&Wl[(nb+g)*40 + kk + 2*t + 8];
                #pragma unroll
                for (int mi = 0; mi < 2; ++mi) {
                    mma16816(acc[mi][ni], aH[mi], bh);
                    mma16816(acc[mi][ni], aL[mi], bh);
                    mma16816(acc[mi][ni], aH[mi], bl);
                }
            }
        }
    };

    int IT = K / 32;
    load_stage(0, 0);
    CP_COMMIT();
    for (int it = 0; it < IT; ++it) {
        if (it + 1 < IT) {
            load_stage((it+1)&1, (it+1)*32);
            CP_COMMIT();
            CP_WAIT(1);
        } else {
            CP_WAIT(0);
        }
        __syncthreads();
        compute_stage(it & 1);
        __syncthreads();
    }

    #pragma unroll
    for (int mi = 0; mi < 2; ++mi)
        #pragma unroll
        for (int ni = 0; ni < NT; ++ni) {
            int row = m0 + wm*32 + mi*16 + g;
            int col = n0 + wn*(NT*8) + ni*8 + 2*t;
            float2* p0 = (float2*)&C[(size_t)row*N + col];
            float2* p1 = (float2*)&C[(size_t)(row + 8)*N + col];
            if (ADD) {
                float2 v0 = *p0, v1 = *p1;
                v0.x += acc[mi][ni][0]; v0.y += acc[mi][ni][1];
                v1.x += acc[mi][ni][2]; v1.y += acc[mi][ni][3];
                *p0 = v0; *p1 = v1;
            } else {
                *p0 = make_float2(acc[mi][ni][0], acc[mi][ni][1]);
                *p1 = make_float2(acc[mi][ni][2], acc[mi][ni][3]);
            }
        }
}

// ---------------- RoPE + convert to fp16 hi/lo (+ V transpose) ---------------
__global__ void k_rope_cvt(const float* __restrict__ qkv,
                           __half* __restrict__ qh, __half* __restrict__ ql,
                           __half* __restrict__ kh, __half* __restrict__ kl,
                           __half* __restrict__ vth, __half* __restrict__ vtl) {
    int idx = blockIdx.x * blockDim.x + threadIdx.x;   // MM*512
    if (idx >= MM*512) return;
    int i    = idx & 31;
    int head = (idx >> 5) & 15;
    int m    = idx >> 9;
    int t    = m & (TT - 1);
    int b    = m >> 10;
    float invf = powf(10000.0f, -(2.0f * i) / 64.0f);
    float ang  = (float)t * invf;
    float c, s;
    sincosf(ang, &s, &c);

    size_t base = (size_t)m*(3*CC) + head*64 + i;
    int col = head*64 + i;
    size_t qo = (size_t)m*CC + col;

    // q (scaled by 1/8)
    {
        float x1 = qkv[base], x2 = qkv[base+32];
        float r1 = (x1*c - x2*s) * 0.125f;
        float r2 = (x2*c + x1*s) * 0.125f;
        __half h1 = __float2half(r1), h2 = __float2half(r2);
        qh[qo]    = h1; ql[qo]    = __float2half(r1 - __half2float(h1));
        qh[qo+32] = h2; ql[qo+32] = __float2half(r2 - __half2float(h2));
    }
    // k
    {
        float x1 = qkv[base+CC], x2 = qkv[base+CC+32];
        float r1 = x1*c - x2*s;
        float r2 = x2*c + x1*s;
        __half h1 = __float2half(r1), h2 = __float2half(r2);
        kh[qo]    = h1; kl[qo]    = __float2half(r1 - __half2float(h1));
        kh[qo+32] = h2; kl[qo+32] = __float2half(r2 - __half2float(h2));
    }
    // v transposed: [b][head][d][t]
    {
        float v1 = qkv[base+2*CC], v2 = qkv[base+2*CC+32];
        size_t o1 = ((size_t)(b*NHH + head)*DHH + i)      * TT + t;
        size_t o2 = ((size_t)(b*NHH + head)*DHH + i + 32) * TT + t;
        __half h1 = __float2half(v1), h2 = __float2half(v2);
        vth[o1] = h1; vtl[o1] = __float2half(v1 - __half2float(h1));
        vth[o2] = h2; vtl[o2] = __float2half(v2 - __half2float(h2));
    }
}

// ---------------- tensor-core flash attention --------------------------------
// grid (T/64, NH, B), 128 threads (4 warps x 16 query rows).
__global__ void k_attn_mma(const __half* __restrict__ qh, const __half* __restrict__ ql,
                           const __half* __restrict__ kh, const __half* __restrict__ kl,
                           const __half* __restrict__ vth, const __half* __restrict__ vtl,
                           __half* __restrict__ y2) {
    __shared__ __half Kh[64][72], Kl[64][72], Vh[64][72], Vl[64][72];

    int tid = threadIdx.x, wid = tid >> 5, lane = tid & 31;
    int g = lane >> 2, t = lane & 3;
    int qt = blockIdx.x, head = blockIdx.y, b = blockIdx.z;

    // preload Q fragments (rows wid*16+g, +8; all 4 k-steps), hi and lo
    unsigned aQh[4][4], aQl[4][4];
    {
        size_t r0 = (size_t)(b*TT + qt*64 + wid*16 + g) * CC + head*64;
        size_t r1 = r0 + 8*CC;
        #pragma unroll
        for (int ks = 0; ks < 4; ++ks) {
            int c0 = ks*16 + 2*t, c1 = c0 + 8;
            aQh[ks][0] = *(const unsigned*)&qh[r0 + c0];
            aQh[ks][1] = *(const unsigned*)&qh[r1 + c0];
            aQh[ks][2] = *(const unsigned*)&qh[r0 + c1];
            aQh[ks][3] = *(const unsigned*)&qh[r1 + c1];
            aQl[ks][0] = *(const unsigned*)&ql[r0 + c0];
            aQl[ks][1] = *(const unsigned*)&ql[r1 + c0];
            aQl[ks][2] = *(const unsigned*)&ql[r0 + c1];
            aQl[ks][3] = *(const unsigned*)&ql[r1 + c1];
        }
    }

    float O[8][4];
    #pragma unroll
    for (int n = 0; n < 8; ++n)
        #pragma unroll
        for (int q = 0; q < 4; ++q) O[n][q] = 0.f;
    float m0 = -INFINITY, m1 = -INFINITY, l0 = 0.f, l1 = 0.f;

    for (int kt = 0; kt <= qt; ++kt) {
        // load K (hi/lo) and V^T (hi/lo) tiles
        #pragma unroll
        for (int i = 0; i < 4; ++i) {
            int cid = tid + i*128;               // 0..511
            int row = cid >> 3, ch = (cid & 7) * 8;
            size_t ksrc = (size_t)(b*TT + kt*64 + row)*CC + head*64 + ch;
            cp16(&Kh[row][ch], kh + ksrc);
            cp16(&Kl[row][ch], kl + ksrc);
            size_t vsrc = ((size_t)(b*NHH + head)*DHH + row)*TT + kt*64 + ch;
            cp16(&Vh[row][ch], vth + vsrc);
            cp16(&Vl[row][ch], vtl + vsrc);
        }
        CP_COMMIT();
        CP_WAIT(0);
        __syncthreads();

        // S = Q K^T (3-term)
        float S[8][4];
        #pragma unroll
        for (int n = 0; n < 8; ++n) {
            S[n][0] = S[n][1] = S[n][2] = S[n][3] = 0.f;
            #pragma unroll
            for (int ks = 0; ks < 4; ++ks) {
                unsigned bh[2], bl[2];
                bh[0] = *(const unsigned*)&Kh[n*8+g][ks*16 + 2*t];
                bh[1] = *(const unsigned*)&Kh[n*8+g][ks*16 + 2*t + 8];
                bl[0] = *(const unsigned*)&Kl[n*8+g][ks*16 + 2*t];
                bl[1] = *(const unsigned*)&Kl[n*8+g][ks*16 + 2*t + 8];
                mma16816(S[n], aQh[ks], bh);
                mma16816(S[n], aQl[ks], bh);
                mma16816(S[n], aQh[ks], bl);
            }
        }

        // causal mask on the diagonal tile
        if (kt == qt) {
            int r0 = wid*16 + g, r1 = r0 + 8;
            #pragma unroll
            for (int n = 0; n < 8; ++n) {
                int c0 = n*8 + 2*t, c1 = c0 + 1;
                if (c0 > r0) S[n][0] = -INFINITY;
                if (c1 > r0) S[n][1] = -INFINITY;
                if (c0 > r1) S[n][2] = -INFINITY;
                if (c1 > r1) S[n][3] = -INFINITY;
            }
        }

        // online softmax (register + quad shuffle)
        float mt0 = -INFINITY, mt1 = -INFINITY;
        #pragma unroll
        for (int n = 0; n < 8; ++n) {
            mt0 = fmaxf(mt0, fmaxf(S[n][0], S[n][1]));
            mt1 = fmaxf(mt1, fmaxf(S[n][2], S[n][3]));
        }
        mt0 = fmaxf(mt0, __shfl_xor_sync(0xffffffffu, mt0, 1));
        mt0 = fmaxf(mt0, __shfl_xor_sync(0xffffffffu, mt0, 2));
        mt1 = fmaxf(mt1, __shfl_xor_sync(0xffffffffu, mt1, 1));
        mt1 = fmaxf(mt1, __shfl_xor_sync(0xffffffffu, mt1, 2));
        float mn0 = fmaxf(m0, mt0), mn1 = fmaxf(m1, mt1);
        float a0 = __expf(m0 - mn0), a1 = __expf(m1 - mn1);
        float ls0 = 0.f, ls1 = 0.f;
        #pragma unroll
        for (int n = 0; n < 8; ++n) {
            S[n][0] = __expf(S[n][0] - mn0);
            S[n][1] = __expf(S[n][1] - mn0);
            S[n][2] = __expf(S[n][2] - mn1);
            S[n][3] = __expf(S[n][3] - mn1);
            ls0 += S[n][0] + S[n][1];
            ls1 += S[n][2] + S[n][3];
        }
        ls0 += __shfl_xor_sync(0xffffffffu, ls0, 1);
        ls0 += __shfl_xor_sync(0xffffffffu, ls0, 2);
        ls1 += __shfl_xor_sync(0xffffffffu, ls1, 1);
        ls1 += __shfl_xor_sync(0xffffffffu, ls1, 2);
        l0 = l0*a0 + ls0;  m0 = mn0;
        l1 = l1*a1 + ls1;  m1 = mn1;
        #pragma unroll
        for (int n = 0; n < 8; ++n) {
            O[n][0] *= a0; O[n][1] *= a0;
            O[n][2] *= a1; O[n][3] *= a1;
        }

        // P fragments (hi/lo) directly from S accums
        unsigned aPh[4][4], aPl[4][4];
        #pragma unroll
        for (int ks = 0; ks < 4; ++ks) {
            pack2(S[2*ks][0],   S[2*ks][1],   aPh[ks][0], aPl[ks][0]);
            pack2(S[2*ks][2],   S[2*ks][3],   aPh[ks][1], aPl[ks][1]);
            pack2(S[2*ks+1][0], S[2*ks+1][1], aPh[ks][2], aPl[ks][2]);
            pack2(S[2*ks+1][2], S[2*ks+1][3], aPh[ks][3], aPl[ks][3]);
        }

        // O += P V (3-term)
        #pragma unroll
        for (int n = 0; n < 8; ++n) {
            #pragma unroll
            for (int ks = 0; ks < 4; ++ks) {
                unsigned bh[2], bl[2];
                bh[0] = *(const unsigned*)&Vh[n*8+g][ks*16 + 2*t];
                bh[1] = *(const unsigned*)&Vh[n*8+g][ks*16 + 2*t + 8];
                bl[0] = *(const unsigned*)&Vl[n*8+g][ks*16 + 2*t];
                bl[1] = *(const unsigned*)&Vl[n*8+g][ks*16 + 2*t + 8];
                mma16816(O[n], aPh[ks], bh);
                mma16816(O[n], aPl[ks], bh);
                mma16816(O[n], aPh[ks], bl);
            }
        }
        __syncthreads();   // before next tile overwrites K/V smem
    }

    // epilogue: normalize + write split fp16
    float i0 = 1.f / l0, i1 = 1.f / l1;
    int row0 = b*TT + qt*64 + wid*16 + g;
    #pragma unroll
    for (int n = 0; n < 8; ++n) {
        int col = head*64 + n*8 + 2*t;
        float v0 = O[n][0]*i0, v1 = O[n][1]*i0;
        float v2 = O[n][2]*i1, v3 = O[n][3]*i1;
        unsigned h01, l01, h23, l23;
        pack2(v0, v1, h01, l01);
        pack2(v2, v3, h23, l23);
        *(unsigned*)&y2[(size_t)row0*2*CC + col]            = h01;
        *(unsigned*)&y2[(size_t)row0*2*CC + CC + col]       = l01;
        *(unsigned*)&y2[(size_t)(row0+8)*2*CC + col]        = h23;
        *(unsigned*)&y2[(size_t)(row0+8)*2*CC + CC + col]   = l23;
    }
}

// ---------------- SiLU gate -> split fp16 ------------------------------------
__global__ void k_silu_h(const float* __restrict__ u1,
                         const float* __restrict__ u2,
                         __half* __restrict__ u12) {   // [M][2*HFF]
    int idx = blockIdx.x * blockDim.x + threadIdx.x;
    if (idx >= MM*HFF_) return;
    int m = idx / HFF_;
    int c = idx - m*HFF_;
    float v = u1[idx];
    float sig = 1.f / (1.f + __expf(-v));
    float gval = v * sig * u2[idx];
    __half hi = __float2half(gval);
    u12[(size_t)m*2*HFF_ + c]        = hi;
    u12[(size_t)m*2*HFF_ + HFF_ + c] = __float2half(gval - __half2float(hi));
}

// ---------------- final RMSNorm into d_out -----------------------------------
__global__ void k_rms_out(const float* __restrict__ in,
                          float* __restrict__ out,
                          const float* __restrict__ g) {
    int m = blockIdx.x;
    const float* r = in + (size_t)m * CC;
    float s = 0.f;
    for (int c = threadIdx.x; c < CC; c += 256) { float v = r[c]; s += v*v; }
    __shared__ float red[256];
    red[threadIdx.x] = s;
    __syncthreads();
    #pragma unroll
    for (int off = 128; off > 0; off >>= 1) {
        if (threadIdx.x < off) red[threadIdx.x] += red[threadIdx.x + off];
        __syncthreads();
    }
    float inv = rsqrtf(red[0] * (1.0f/CC) + 1e-5f);
    for (int c = threadIdx.x; c < CC; c += 256)
        out[(size_t)m*CC + c] = r[c] * inv * g[c];
}

// ---------------- orchestration ----------------------------------------------
extern "C" void kernel_launch(void* const* d_in, const int* in_sizes, int n_in,
                              void* d_out, int out_size) {
    const float* x    = (const float*)d_in[0];
    const float* w_in = (const float*)d_in[1];
    const float* wq   = (const float*)d_in[2];
    const float* wkv  = (const float*)d_in[3];
    const float* wo   = (const float*)d_in[4];
    const float* w1   = (const float*)d_in[5];
    const float* w2   = (const float*)d_in[6];
    const float* w3   = (const float*)d_in[7];
    const float* g1   = (const float*)d_in[8];
    const float* g2   = (const float*)d_in[9];
    const float* gf   = (const float*)d_in[10];
    float* out = (float*)d_out;

    float *h, *qkvb, *u1, *u2;
    __half *a2, *y2, *u12, *wqkv2, *wo2, *w12, *w22, *w32;
    __half *qhp, *qlp, *khp, *klp, *vthp, *vtlp;
    cudaGetSymbolAddress((void**)&h,    g_h);
    cudaGetSymbolAddress((void**)&a2,   g_a2);
    cudaGetSymbolAddress((void**)&qkvb, g_qkv);
    cudaGetSymbolAddress((void**)&qhp,  g_qh);
    cudaGetSymbolAddress((void**)&qlp,  g_ql);
    cudaGetSymbolAddress((void**)&khp,  g_kh);
    cudaGetSymbolAddress((void**)&klp,  g_kl);
    cudaGetSymbolAddress((void**)&vthp, g_vth);
    cudaGetSymbolAddress((void**)&vtlp, g_vtl);
    cudaGetSymbolAddress((void**)&y2,   g_y2);
    cudaGetSymbolAddress((void**)&u1,   g_u1);
    cudaGetSymbolAddress((void**)&u2,   g_u2);
    cudaGetSymbolAddress((void**)&u12,  g_u12);
    cudaGetSymbolAddress((void**)&wqkv2,g_wqkv2);
    cudaGetSymbolAddress((void**)&wo2,  g_wo2);
    cudaGetSymbolAddress((void**)&w12,  g_w12);
    cudaGetSymbolAddress((void**)&w22,  g_w22);
    cudaGetSymbolAddress((void**)&w32,  g_w32);

    const int SMEM128 = (2*(2*128 + 2*128)*40) * (int)sizeof(__half);  // 81920
    const int SMEM64  = (2*(2*128 + 2*64 )*40) * (int)sizeof(__half);  // 61440
    cudaFuncSetAttribute(k_hgemm<128,false>,
                         cudaFuncAttributeMaxDynamicSharedMemorySize, SMEM128);
    cudaFuncSetAttribute(k_hgemm<64,true>,
                         cudaFuncAttributeMaxDynamicSharedMemorySize, SMEM64);

    // weight splits
    {
        int n;
        n = LLAYERS*3*CC*CC;
        k_split_qkv_w<<<(n+255)/256, 256>>>(wq, wkv, wqkv2);
        n = LLAYERS*CC*CC;
        k_split_w<<<(n+255)/256, 256>>>(wo, wo2, n, CC);
        n = LLAYERS*HFF_*CC;
        k_split_w<<<(n+255)/256, 256>>>(w1, w12, n, CC);
        k_split_w<<<(n+255)/256, 256>>>(w2, w22, n, CC);
        n = LLAYERS*CC*HFF_;
        k_split_w<<<(n+255)/256, 256>>>(w3, w32, n, HFF_);
    }

    k_input_proj<<<MM*CC/256, 256>>>(x, w_in, h);

    for (int l = 0; l < LLAYERS; ++l) {
        const __half* wqkv_l = wqkv2 + (size_t)l*3*CC*2*CC;
        const __half* wo_l   = wo2   + (size_t)l*CC*2*CC;
        const __half* w1_l   = w12   + (size_t)l*HFF_*2*CC;
        const __half* w2_l   = w22   + (size_t)l*HFF_*2*CC;
        const __half* w3_l   = w32   + (size_t)l*CC*2*HFF_;

        // --- attention block ---
        k_rms_h<<<MM, 256>>>(h, a2, g1 + l*CC);
        k_hgemm<128,false><<<dim3(3*CC/128, MM/128), 256, SMEM128>>>(a2, wqkv_l, qkvb, MM, 3*CC, CC);
        k_rope_cvt<<<(MM*512)/256, 256>>>(qkvb, qhp, qlp, khp, klp, vthp, vtlp);
        k_attn_mma<<<dim3(TT/64, NHH, BB), 128>>>(qhp, qlp, khp, klp, vthp, vtlp, y2);
        k_hgemm<64,true><<<dim3(CC/64, MM/128), 256, SMEM64>>>(y2, wo_l, h, MM, CC, CC);

        // --- MLP block ---
        k_rms_h<<<MM, 256>>>(h, a2, g2 + l*CC);
        k_hgemm<128,false><<<dim3(HFF_/128, MM/128), 256, SMEM128>>>(a2, w1_l, u1, MM, HFF_, CC);
        k_hgemm<128,false><<<dim3(HFF_/128, MM/128), 256, SMEM128>>>(a2, w2_l, u2, MM, HFF_, CC);
        k_silu_h<<<(MM*HFF_+255)/256, 256>>>(u1, u2, u12);
        k_hgemm<64,true><<<dim3(CC/64, MM/128), 256, SMEM64>>>(u12, w3_l, h, MM, CC, HFF_);
    }

    k_rms_out<<<MM, 256>>>(h, out, gf);
}

// round 4
// speedup vs baseline: 3.2004x; 1.2868x over previous
#include <cuda_runtime.h>
#include <cuda_fp16.h>
#include <math.h>

#define BB   2
#define TT   1024
#define CC   1024
#define NHH  16
#define DHH  64
#define LLAYERS 4
#define HFF_ 2816
#define MM   (BB*TT)          // 2048 rows

// ---------------- scratch (static device globals) ---------------------------
__device__ __align__(16) float  g_h   [MM*CC];
__device__ __align__(16) __half g_a2  [MM*2*CC];     // rms acts [hi|lo]
__device__ __align__(16) float  g_qkv [MM*3*CC];     // fused q|k|v (fp32)
__device__ __align__(16) __half g_qh  [MM*CC];       // roped q hi (pre-scaled)
__device__ __align__(16) __half g_ql  [MM*CC];
__device__ __align__(16) __half g_kh  [MM*CC];
__device__ __align__(16) __half g_kl  [MM*CC];
__device__ __align__(16) __half g_vth [MM*CC];       // V^T [b][h][d][t] hi
__device__ __align__(16) __half g_vtl [MM*CC];
__device__ __align__(16) __half g_y2  [MM*2*CC];     // attn out [hi|lo]
__device__ __align__(16) float  g_u1  [MM*HFF_];
__device__ __align__(16) float  g_u2  [MM*HFF_];
__device__ __align__(16) __half g_u12 [MM*2*HFF_];

// split fp16 weights, row layout [row][hi(K) | lo(K)]
__device__ __align__(16) __half g_wqkv2[LLAYERS*3*CC*2*CC];
__device__ __align__(16) __half g_wo2  [LLAYERS*CC*2*CC];
__device__ __align__(16) __half g_w12  [LLAYERS*HFF_*2*CC];
__device__ __align__(16) __half g_w22  [LLAYERS*HFF_*2*CC];
__device__ __align__(16) __half g_w32  [LLAYERS*CC*2*HFF_];

// ---------------- helpers ----------------------------------------------------
__device__ __forceinline__ void cp16(void* smem_dst, const void* gsrc) {
    unsigned d = (unsigned)__cvta_generic_to_shared(smem_dst);
    asm volatile("cp.async.ca.shared.global [%0], [%1], 16;\n" :: "r"(d), "l"(gsrc));
}
#define CP_COMMIT()  asm volatile("cp.async.commit_group;\n")
#define CP_WAIT(N)   asm volatile("cp.async.wait_group %0;\n" :: "n"(N))

__device__ __forceinline__ void mma16816(float* d, const unsigned* a, const unsigned* b) {
    asm volatile(
        "mma.sync.aligned.m16n8k16.row.col.f32.f16.f16.f32 "
        "{%0,%1,%2,%3}, {%4,%5,%6,%7}, {%8,%9}, {%0,%1,%2,%3};\n"
        : "+f"(d[0]), "+f"(d[1]), "+f"(d[2]), "+f"(d[3])
        : "r"(a[0]), "r"(a[1]), "r"(a[2]), "r"(a[3]), "r"(b[0]), "r"(b[1]));
}

__device__ __forceinline__ void ldsm4(unsigned addr, unsigned& r0, unsigned& r1,
                                      unsigned& r2, unsigned& r3) {
    asm volatile("ldmatrix.sync.aligned.m8n8.x4.shared.b16 {%0,%1,%2,%3}, [%4];\n"
                 : "=r"(r0), "=r"(r1), "=r"(r2), "=r"(r3) : "r"(addr));
}

__device__ __forceinline__ unsigned packh2(__half a, __half b) {
    return (unsigned)__half_as_ushort(a) | ((unsigned)__half_as_ushort(b) << 16);
}
__device__ __forceinline__ void pack2(float x, float y, unsigned& hi, unsigned& lo) {
    __half hx = __float2half(x), hy = __float2half(y);
    __half lx = __float2half(x - __half2float(hx));
    __half ly = __float2half(y - __half2float(hy));
    hi = packh2(hx, hy);
    lo = packh2(lx, ly);
}

// ---------------- weight split conversion (vectorized) -----------------------
__global__ void k_split_w4(const float* __restrict__ src, __half* __restrict__ dst,
                           int total4, int K) {
    int idx = blockIdx.x * blockDim.x + threadIdx.x;
    if (idx >= total4) return;
    int i4 = idx * 4;
    int r = i4 / K;
    int k = i4 - r * K;
    float4 v = *(const float4*)&src[i4];
    __half h0 = __float2half(v.x), h1 = __float2half(v.y);
    __half h2 = __float2half(v.z), h3 = __float2half(v.w);
    __half l0 = __float2half(v.x - __half2float(h0));
    __half l1 = __float2half(v.y - __half2float(h1));
    __half l2 = __float2half(v.z - __half2float(h2));
    __half l3 = __float2half(v.w - __half2float(h3));
    size_t off = (size_t)r*2*K + k;
    uint2 uh; uh.x = packh2(h0,h1); uh.y = packh2(h2,h3);
    uint2 ul; ul.x = packh2(l0,l1); ul.y = packh2(l2,l3);
    *(uint2*)&dst[off]     = uh;
    *(uint2*)&dst[off + K] = ul;
}

__global__ void k_split_qkv_w4(const float* __restrict__ wq,
                               const float* __restrict__ wkv,
                               __half* __restrict__ dst) {
    int idx = blockIdx.x * blockDim.x + threadIdx.x;
    if (idx >= LLAYERS*3*CC*CC/4) return;
    int i4  = idx * 4;
    int l   = i4 / (3*CC*CC);
    int rem = i4 - l*(3*CC*CC);
    int row = rem >> 10;
    int k   = rem & 1023;
    float4 v = (row < CC)
        ? *(const float4*)&wq [((size_t)l*CC   + row)      * CC + k]
        : *(const float4*)&wkv[((size_t)l*2*CC + (row-CC)) * CC + k];
    __half h0 = __float2half(v.x), h1 = __float2half(v.y);
    __half h2 = __float2half(v.z), h3 = __float2half(v.w);
    __half l0 = __float2half(v.x - __half2float(h0));
    __half l1 = __float2half(v.y - __half2float(h1));
    __half l2 = __float2half(v.z - __half2float(h2));
    __half l3 = __float2half(v.w - __half2float(h3));
    __half* d = dst + ((size_t)l*3*CC + row)*2*CC;
    uint2 uh; uh.x = packh2(h0,h1); uh.y = packh2(h2,h3);
    uint2 ul; ul.x = packh2(l0,l1); ul.y = packh2(l2,l3);
    *(uint2*)&d[k]      = uh;
    *(uint2*)&d[CC + k] = ul;
}

// ---------------- input projection: h = x @ w_in^T  (K=9) --------------------
__global__ void k_input_proj(const float* __restrict__ x,
                             const float* __restrict__ w,
                             float* __restrict__ h) {
    int idx = blockIdx.x * blockDim.x + threadIdx.x;
    if (idx >= MM*CC) return;
    int m = idx >> 10;
    int c = idx & 1023;
    const float* xr = x + m*9;
    const float* wr = w + c*9;
    float s = 0.f;
    #pragma unroll
    for (int f = 0; f < 9; ++f) s += xr[f] * wr[f];
    h[idx] = s;
}

// ---------------- RMSNorm -> split fp16 hi/lo (vectorized) -------------------
__global__ void k_rms_h(const float* __restrict__ in,
                        __half* __restrict__ out2,     // [M][2C]
                        const float* __restrict__ g) {
    int m = blockIdx.x;
    int c4 = threadIdx.x * 4;
    float4 v = *(const float4*)&in[(size_t)m*CC + c4];
    float s = v.x*v.x + v.y*v.y + v.z*v.z + v.w*v.w;
    __shared__ float red[256];
    red[threadIdx.x] = s;
    __syncthreads();
    #pragma unroll
    for (int off = 128; off > 0; off >>= 1) {
        if (threadIdx.x < off) red[threadIdx.x] += red[threadIdx.x + off];
        __syncthreads();
    }
    float inv = rsqrtf(red[0] * (1.0f/CC) + 1e-5f);
    float4 gv = *(const float4*)&g[c4];
    float o0 = v.x*inv*gv.x, o1 = v.y*inv*gv.y;
    float o2 = v.z*inv*gv.z, o3 = v.w*inv*gv.w;
    unsigned h01, l01, h23, l23;
    pack2(o0, o1, h01, l01);
    pack2(o2, o3, h23, l23);
    uint2 uh; uh.x = h01; uh.y = h23;
    uint2 ul; ul.x = l01; ul.y = l23;
    *(uint2*)&out2[(size_t)m*2*CC + c4]      = uh;
    *(uint2*)&out2[(size_t)m*2*CC + CC + c4] = ul;
}

// ---------------- pipelined ldmatrix fp16x3 tensor-core GEMM -----------------
// C[M,N] (+)= A[M,K]*W[N,K]^T as Ahi*Whi + Alo*Whi + Ahi*Wlo, single K pass.
// BM=BN=128, BK=32, 3-stage cp.async, 256 threads (8 warps, 4m x 2n, 32x64 warp tile).
// Stage layout: rows [Ah(128) | Al(128) | Wh(128) | Wl(128)], row stride 40 halves.
#define GSTG 20480            // halves per stage (512 rows * 40)
#define GSMEM (3*GSTG*2)      // bytes = 122880
template<bool ADD>
__global__ void k_hgemm(const __half* __restrict__ A,
                        const __half* __restrict__ W,
                        float* __restrict__ C,
                        int M, int N, int K) {
    extern __shared__ __half sh[];
    int tid  = threadIdx.x;
    int wid  = tid >> 5, lane = tid & 31;
    int wm   = wid & 3,  wn   = wid >> 2;
    int g    = lane >> 2, t   = lane & 3;
    int m0   = blockIdx.y * 128, n0 = blockIdx.x * 128;
    int ld   = 2 * K;

    unsigned sb = (unsigned)__cvta_generic_to_shared(sh);
    // ldmatrix per-lane offsets (bytes), row stride 80B
    unsigned aOff = (lane & 15)*80 + (lane >> 4)*16;
    unsigned bOff = ((lane & 7) + ((lane >> 4) << 3))*80 + ((lane >> 3) & 1)*16;

    float acc[2][8][4];
    #pragma unroll
    for (int mi = 0; mi < 2; ++mi)
        #pragma unroll
        for (int ni = 0; ni < 8; ++ni)
            #pragma unroll
            for (int q = 0; q < 4; ++q) acc[mi][ni][q] = 0.f;

    auto load_stage = [&](int st, int k0) {
        __half* base = sh + st*GSTG;
        #pragma unroll
        for (int i = 0; i < 8; ++i) {
            int c   = tid + i*256;          // 0..2047
            int row = c >> 2;
            int kc  = (c & 3) * 8;
            const __half* src;
            if      (row < 128) src = A + (size_t)(m0 + row      )*ld + k0 + kc;
            else if (row < 256) src = A + (size_t)(m0 + row - 128)*ld + K + k0 + kc;
            else if (row < 384) src = W + (size_t)(n0 + row - 256)*ld + k0 + kc;
            else                src = W + (size_t)(n0 + row - 384)*ld + K + k0 + kc;
            cp16(base + row*40 + kc, src);
        }
    };

    auto compute_stage = [&](int st) {
        unsigned base = sb + st*(GSTG*2);
        unsigned aHb = base + (wm*32)*80 + aOff;
        unsigned aLb = aHb + 128*80;
        unsigned bHb = base + 256*80 + (wn*64)*80 + bOff;
        unsigned bLb = bHb + 128*80;
        #pragma unroll
        for (int kk = 0; kk < 32; kk += 16) {
            unsigned aH[2][4], aL[2][4], bh[8][2], bl[8][2];
            #pragma unroll
            for (int mi = 0; mi < 2; ++mi) {
                ldsm4(aHb + mi*16*80 + kk*2, aH[mi][0], aH[mi][1], aH[mi][2], aH[mi][3]);
                ldsm4(aLb + mi*16*80 + kk*2, aL[mi][0], aL[mi][1], aL[mi][2], aL[mi][3]);
            }
            #pragma unroll
            for (int nj = 0; nj < 4; ++nj) {
                ldsm4(bHb + nj*16*80 + kk*2,
                      bh[2*nj][0], bh[2*nj][1], bh[2*nj+1][0], bh[2*nj+1][1]);
                ldsm4(bLb + nj*16*80 + kk*2,
                      bl[2*nj][0], bl[2*nj][1], bl[2*nj+1][0], bl[2*nj+1][1]);
            }
            #pragma unroll
            for (int ni = 0; ni < 8; ++ni)
                #pragma unroll
                for (int mi = 0; mi < 2; ++mi) {
                    mma16816(acc[mi][ni], aH[mi], bh[ni]);
                    mma16816(acc[mi][ni], aL[mi], bh[ni]);
                    mma16816(acc[mi][ni], aH[mi], bl[ni]);
                }
        }
    };

    int IT = K / 32;
    load_stage(0, 0);  CP_COMMIT();
    load_stage(1, 32); CP_COMMIT();
    for (int it = 0; it < IT; ++it) {
        CP_WAIT(1);
        __syncthreads();
        if (it + 2 < IT) load_stage((it+2)%3, (it+2)*32);
        CP_COMMIT();
        compute_stage(it % 3);
    }

    #pragma unroll
    for (int mi = 0; mi < 2; ++mi)
        #pragma unroll
        for (int ni = 0; ni < 8; ++ni) {
            int row = m0 + wm*32 + mi*16 + g;
            int col = n0 + wn*64 + ni*8 + 2*t;
            float2* p0 = (float2*)&C[(size_t)row*N + col];
            float2* p1 = (float2*)&C[(size_t)(row + 8)*N + col];
            if (ADD) {
                float2 v0 = *p0, v1 = *p1;
                v0.x += acc[mi][ni][0]; v0.y += acc[mi][ni][1];
                v1.x += acc[mi][ni][2]; v1.y += acc[mi][ni][3];
                *p0 = v0; *p1 = v1;
            } else {
                *p0 = make_float2(acc[mi][ni][0], acc[mi][ni][1]);
                *p1 = make_float2(acc[mi][ni][2], acc[mi][ni][3]);
            }
        }
}

// ---------------- RoPE + convert to fp16 hi/lo (+ V transpose) ---------------
__global__ void k_rope_cvt(const float* __restrict__ qkv,
                           __half* __restrict__ qh, __half* __restrict__ ql,
                           __half* __restrict__ kh, __half* __restrict__ kl,
                           __half* __restrict__ vth, __half* __restrict__ vtl) {
    int idx = blockIdx.x * blockDim.x + threadIdx.x;   // MM*512
    if (idx >= MM*512) return;
    int i    = idx & 31;
    int head = (idx >> 5) & 15;
    int m    = idx >> 9;
    int t    = m & (TT - 1);
    int b    = m >> 10;
    float invf = __powf(10000.0f, -(2.0f * i) / 64.0f);
    float ang  = (float)t * invf;
    float c, s;
    __sincosf(ang, &s, &c);

    size_t base = (size_t)m*(3*CC) + head*64 + i;
    int col = head*64 + i;
    size_t qo = (size_t)m*CC + col;

    // q (scaled by 1/8)
    {
        float x1 = qkv[base], x2 = qkv[base+32];
        float r1 = (x1*c - x2*s) * 0.125f;
        float r2 = (x2*c + x1*s) * 0.125f;
        __half h1 = __float2half(r1), h2 = __float2half(r2);
        qh[qo]    = h1; ql[qo]    = __float2half(r1 - __half2float(h1));
        qh[qo+32] = h2; ql[qo+32] = __float2half(r2 - __half2float(h2));
    }
    // k
    {
        float x1 = qkv[base+CC], x2 = qkv[base+CC+32];
        float r1 = x1*c - x2*s;
        float r2 = x2*c + x1*s;
        __half h1 = __float2half(r1), h2 = __float2half(r2);
        kh[qo]    = h1; kl[qo]    = __float2half(r1 - __half2float(h1));
        kh[qo+32] = h2; kl[qo+32] = __float2half(r2 - __half2float(h2));
    }
    // v transposed: [b][head][d][t]
    {
        float v1 = qkv[base+2*CC], v2 = qkv[base+2*CC+32];
        size_t o1 = ((size_t)(b*NHH + head)*DHH + i)      * TT + t;
        size_t o2 = ((size_t)(b*NHH + head)*DHH + i + 32) * TT + t;
        __half h1 = __float2half(v1), h2 = __float2half(v2);
        vth[o1] = h1; vtl[o1] = __float2half(v1 - __half2float(h1));
        vth[o2] = h2; vtl[o2] = __float2half(v2 - __half2float(h2));
    }
}

// ---------------- tensor-core flash attention (double-buffered) --------------
// grid (T/64, NH, B), 128 threads (4 warps x 16 query rows).
#define ASTG 18432              // halves per stage: 4 arrays * 64*72
#define ASMEM (2*ASTG*2)        // bytes = 73728
__global__ void k_attn_mma(const __half* __restrict__ qh, const __half* __restrict__ ql,
                           const __half* __restrict__ kh, const __half* __restrict__ kl,
                           const __half* __restrict__ vth, const __half* __restrict__ vtl,
                           __half* __restrict__ y2) {
    extern __shared__ __half ash[];

    int tid = threadIdx.x, wid = tid >> 5, lane = tid & 31;
    int g = lane >> 2, t = lane & 3;
    int qt = blockIdx.x, head = blockIdx.y, b = blockIdx.z;

    auto load_tile = [&](int st, int kt) {
        __half* Kh = ash + st*ASTG;
        __half* Kl = Kh + 4608;
        __half* Vh = Kl + 4608;
        __half* Vl = Vh + 4608;
        #pragma unroll
        for (int i = 0; i < 4; ++i) {
            int cid = tid + i*128;               // 0..511
            int row = cid >> 3, ch = (cid & 7) * 8;
            size_t ksrc = (size_t)(b*TT + kt*64 + row)*CC + head*64 + ch;
            cp16(&Kh[row*72 + ch], kh + ksrc);
            cp16(&Kl[row*72 + ch], kl + ksrc);
            size_t vsrc = ((size_t)(b*NHH + head)*DHH + row)*TT + kt*64 + ch;
            cp16(&Vh[row*72 + ch], vth + vsrc);
            cp16(&Vl[row*72 + ch], vtl + vsrc);
        }
    };

    // preload Q fragments (rows wid*16+g, +8; all 4 k-steps), hi and lo
    unsigned aQh[4][4], aQl[4][4];
    {
        size_t r0 = (size_t)(b*TT + qt*64 + wid*16 + g) * CC + head*64;
        size_t r1 = r0 + 8*CC;
        #pragma unroll
        for (int ks = 0; ks < 4; ++ks) {
            int c0 = ks*16 + 2*t, c1 = c0 + 8;
            aQh[ks][0] = *(const unsigned*)&qh[r0 + c0];
            aQh[ks][1] = *(const unsigned*)&qh[r1 + c0];
            aQh[ks][2] = *(const unsigned*)&qh[r0 + c1];
            aQh[ks][3] = *(const unsigned*)&qh[r1 + c1];
            aQl[ks][0] = *(const unsigned*)&ql[r0 + c0];
            aQl[ks][1] = *(const unsigned*)&ql[r1 + c0];
            aQl[ks][2] = *(const unsigned*)&ql[r0 + c1];
            aQl[ks][3] = *(const unsigned*)&ql[r1 + c1];
        }
    }

    float O[8][4];
    #pragma unroll
    for (int n = 0; n < 8; ++n)
        #pragma unroll
        for (int q = 0; q < 4; ++q) O[n][q] = 0.f;
    float m0 = -INFINITY, m1 = -INFINITY, l0 = 0.f, l1 = 0.f;

    int st = 0;
    load_tile(0, 0);
    CP_COMMIT();

    for (int kt = 0; kt <= qt; ++kt) {
        if (kt + 1 <= qt) {
            load_tile(st ^ 1, kt + 1);
            CP_COMMIT();
            CP_WAIT(1);
        } else {
            CP_WAIT(0);
        }
        __syncthreads();

        __half* Kh = ash + st*ASTG;
        __half* Kl = Kh + 4608;
        __half* Vh = Kl + 4608;
        __half* Vl = Vh + 4608;

        // S = Q K^T (3-term)
        float S[8][4];
        #pragma unroll
        for (int n = 0; n < 8; ++n) {
            S[n][0] = S[n][1] = S[n][2] = S[n][3] = 0.f;
            #pragma unroll
            for (int ks = 0; ks < 4; ++ks) {
                unsigned bh[2], bl[2];
                bh[0] = *(const unsigned*)&Kh[(n*8+g)*72 + ks*16 + 2*t];
                bh[1] = *(const unsigned*)&Kh[(n*8+g)*72 + ks*16 + 2*t + 8];
                bl[0] = *(const unsigned*)&Kl[(n*8+g)*72 + ks*16 + 2*t];
                bl[1] = *(const unsigned*)&Kl[(n*8+g)*72 + ks*16 + 2*t + 8];
                mma16816(S[n], aQh[ks], bh);
                mma16816(S[n], aQl[ks], bh);
                mma16816(S[n], aQh[ks], bl);
            }
        }

        // causal mask on the diagonal tile
        if (kt == qt) {
            int r0 = wid*16 + g, r1 = r0 + 8;
            #pragma unroll
            for (int n = 0; n < 8; ++n) {
                int c0 = n*8 + 2*t, c1 = c0 + 1;
                if (c0 > r0) S[n][0] = -INFINITY;
                if (c1 > r0) S[n][1] = -INFINITY;
                if (c0 > r1) S[n][2] = -INFINITY;
                if (c1 > r1) S[n][3] = -INFINITY;
            }
        }

        // online softmax (register + quad shuffle)
        float mt0 = -INFINITY, mt1 = -INFINITY;
        #pragma unroll
        for (int n = 0; n < 8; ++n) {
            mt0 = fmaxf(mt0, fmaxf(S[n][0], S[n][1]));
            mt1 = fmaxf(mt1, fmaxf(S[n][2], S[n][3]));
        }
        mt0 = fmaxf(mt0, __shfl_xor_sync(0xffffffffu, mt0, 1));
        mt0 = fmaxf(mt0, __shfl_xor_sync(0xffffffffu, mt0, 2));
        mt1 = fmaxf(mt1, __shfl_xor_sync(0xffffffffu, mt1, 1));
        mt1 = fmaxf(mt1, __shfl_xor_sync(0xffffffffu, mt1, 2));
        float mn0 = fmaxf(m0, mt0), mn1 = fmaxf(m1, mt1);
        float a0 = __expf(m0 - mn0), a1 = __expf(m1 - mn1);
        float ls0 = 0.f, ls1 = 0.f;
        #pragma unroll
        for (int n = 0; n < 8; ++n) {
            S[n][0] = __expf(S[n][0] - mn0);
            S[n][1] = __expf(S[n][1] - mn0);
            S[n][2] = __expf(S[n][2] - mn1);
            S[n][3] = __expf(S[n][3] - mn1);
            ls0 += S[n][0] + S[n][1];
            ls1 += S[n][2] + S[n][3];
        }
        ls0 += __shfl_xor_sync(0xffffffffu, ls0, 1);
        ls0 += __shfl_xor_sync(0xffffffffu, ls0, 2);
        ls1 += __shfl_xor_sync(0xffffffffu, ls1, 1);
        ls1 += __shfl_xor_sync(0xffffffffu, ls1, 2);
        l0 = l0*a0 + ls0;  m0 = mn0;
        l1 = l1*a1 + ls1;  m1 = mn1;
        #pragma unroll
        for (int n = 0; n < 8; ++n) {
            O[n][0] *= a0; O[n][1] *= a0;
            O[n][2] *= a1; O[n][3] *= a1;
        }

        // P fragments (hi/lo) directly from S accums
        unsigned aPh[4][4], aPl[4][4];
        #pragma unroll
        for (int ks = 0; ks < 4; ++ks) {
            pack2(S[2*ks][0],   S[2*ks][1],   aPh[ks][0], aPl[ks][0]);
            pack2(S[2*ks][2],   S[2*ks][3],   aPh[ks][1], aPl[ks][1]);
            pack2(S[2*ks+1][0], S[2*ks+1][1], aPh[ks][2], aPl[ks][2]);
            pack2(S[2*ks+1][2], S[2*ks+1][3], aPh[ks][3], aPl[ks][3]);
        }

        // O += P V (3-term)
        #pragma unroll
        for (int n = 0; n < 8; ++n) {
            #pragma unroll
            for (int ks = 0; ks < 4; ++ks) {
                unsigned bh[2], bl[2];
                bh[0] = *(const unsigned*)&Vh[(n*8+g)*72 + ks*16 + 2*t];
                bh[1] = *(const unsigned*)&Vh[(n*8+g)*72 + ks*16 + 2*t + 8];
                bl[0] = *(const unsigned*)&Vl[(n*8+g)*72 + ks*16 + 2*t];
                bl[1] = *(const unsigned*)&Vl[(n*8+g)*72 + ks*16 + 2*t + 8];
                mma16816(O[n], aPh[ks], bh);
                mma16816(O[n], aPl[ks], bh);
                mma16816(O[n], aPh[ks], bl);
            }
        }
        __syncthreads();   // protect stage before next prefetch overwrites it
        st ^= 1;
    }

    // epilogue: normalize + write split fp16
    float i0 = 1.f / l0, i1 = 1.f / l1;
    int row0 = b*TT + qt*64 + wid*16 + g;
    #pragma unroll
    for (int n = 0; n < 8; ++n) {
        int col = head*64 + n*8 + 2*t;
        float v0 = O[n][0]*i0, v1 = O[n][1]*i0;
        float v2 = O[n][2]*i1, v3 = O[n][3]*i1;
        unsigned h01, l01, h23, l23;
        pack2(v0, v1, h01, l01);
        pack2(v2, v3, h23, l23);
        *(unsigned*)&y2[(size_t)row0*2*CC + col]            = h01;
        *(unsigned*)&y2[(size_t)row0*2*CC + CC + col]       = l01;
        *(unsigned*)&y2[(size_t)(row0+8)*2*CC + col]        = h23;
        *(unsigned*)&y2[(size_t)(row0+8)*2*CC + CC + col]   = l23;
    }
}

// ---------------- SiLU gate -> split fp16 (vectorized) -----------------------
__global__ void k_silu_h4(const float* __restrict__ u1,
                          const float* __restrict__ u2,
                          __half* __restrict__ u12) {   // [M][2*HFF]
    int idx = blockIdx.x * blockDim.x + threadIdx.x;
    if (idx >= MM*HFF_/4) return;
    int i4 = idx * 4;
    int m = i4 / HFF_;
    int c = i4 - m*HFF_;
    float4 a = *(const float4*)&u1[i4];
    float4 bv = *(const float4*)&u2[i4];
    float o0 = a.x / (1.f + __expf(-a.x)) * bv.x;
    float o1 = a.y / (1.f + __expf(-a.y)) * bv.y;
    float o2 = a.z / (1.f + __expf(-a.z)) * bv.z;
    float o3 = a.w / (1.f + __expf(-a.w)) * bv.w;
    unsigned h01, l01, h23, l23;
    pack2(o0, o1, h01, l01);
    pack2(o2, o3, h23, l23);
    uint2 uh; uh.x = h01; uh.y = h23;
    uint2 ul; ul.x = l01; ul.y = l23;
    *(uint2*)&u12[(size_t)m*2*HFF_ + c]        = uh;
    *(uint2*)&u12[(size_t)m*2*HFF_ + HFF_ + c] = ul;
}

// ---------------- final RMSNorm into d_out (vectorized) ----------------------
__global__ void k_rms_out4(const float* __restrict__ in,
                           float* __restrict__ out,
                           const float* __restrict__ g) {
    int m = blockIdx.x;
    int c4 = threadIdx.x * 4;
    float4 v = *(const float4*)&in[(size_t)m*CC + c4];
    float s = v.x*v.x + v.y*v.y + v.z*v.z + v.w*v.w;
    __shared__ float red[256];
    red[threadIdx.x] = s;
    __syncthreads();
    #pragma unroll
    for (int off = 128; off > 0; off >>= 1) {
        if (threadIdx.x < off) red[threadIdx.x] += red[threadIdx.x + off];
        __syncthreads();
    }
    float inv = rsqrtf(red[0] * (1.0f/CC) + 1e-5f);
    float4 gv = *(const float4*)&g[c4];
    float4 o;
    o.x = v.x*inv*gv.x; o.y = v.y*inv*gv.y;
    o.z = v.z*inv*gv.z; o.w = v.w*inv*gv.w;
    *(float4*)&out[(size_t)m*CC + c4] = o;
}

// ---------------- orchestration ----------------------------------------------
extern "C" void kernel_launch(void* const* d_in, const int* in_sizes, int n_in,
                              void* d_out, int out_size) {
    const float* x    = (const float*)d_in[0];
    const float* w_in = (const float*)d_in[1];
    const float* wq   = (const float*)d_in[2];
    const float* wkv  = (const float*)d_in[3];
    const float* wo   = (const float*)d_in[4];
    const float* w1   = (const float*)d_in[5];
    const float* w2   = (const float*)d_in[6];
    const float* w3   = (const float*)d_in[7];
    const float* g1   = (const float*)d_in[8];
    const float* g2   = (const float*)d_in[9];
    const float* gf   = (const float*)d_in[10];
    float* out = (float*)d_out;

    float *h, *qkvb, *u1, *u2;
    __half *a2, *y2, *u12, *wqkv2, *wo2, *w12, *w22, *w32;
    __half *qhp, *qlp, *khp, *klp, *vthp, *vtlp;
    cudaGetSymbolAddress((void**)&h,    g_h);
    cudaGetSymbolAddress((void**)&a2,   g_a2);
    cudaGetSymbolAddress((void**)&qkvb, g_qkv);
    cudaGetSymbolAddress((void**)&qhp,  g_qh);
    cudaGetSymbolAddress((void**)&qlp,  g_ql);
    cudaGetSymbolAddress((void**)&khp,  g_kh);
    cudaGetSymbolAddress((void**)&klp,  g_kl);
    cudaGetSymbolAddress((void**)&vthp, g_vth);
    cudaGetSymbolAddress((void**)&vtlp, g_vtl);
    cudaGetSymbolAddress((void**)&y2,   g_y2);
    cudaGetSymbolAddress((void**)&u1,   g_u1);
    cudaGetSymbolAddress((void**)&u2,   g_u2);
    cudaGetSymbolAddress((void**)&u12,  g_u12);
    cudaGetSymbolAddress((void**)&wqkv2,g_wqkv2);
    cudaGetSymbolAddress((void**)&wo2,  g_wo2);
    cudaGetSymbolAddress((void**)&w12,  g_w12);
    cudaGetSymbolAddress((void**)&w22,  g_w22);
    cudaGetSymbolAddress((void**)&w32,  g_w32);

    cudaFuncSetAttribute(k_hgemm<false>,
                         cudaFuncAttributeMaxDynamicSharedMemorySize, GSMEM);
    cudaFuncSetAttribute(k_hgemm<true>,
                         cudaFuncAttributeMaxDynamicSharedMemorySize, GSMEM);
    cudaFuncSetAttribute(k_attn_mma,
                         cudaFuncAttributeMaxDynamicSharedMemorySize, ASMEM);

    // weight splits (vectorized)
    {
        int n;
        n = LLAYERS*3*CC*CC/4;
        k_split_qkv_w4<<<(n+255)/256, 256>>>(wq, wkv, wqkv2);
        n = LLAYERS*CC*CC;
        k_split_w4<<<(n/4+255)/256, 256>>>(wo, wo2, n/4, CC);
        n = LLAYERS*HFF_*CC;
        k_split_w4<<<(n/4+255)/256, 256>>>(w1, w12, n/4, CC);
        k_split_w4<<<(n/4+255)/256, 256>>>(w2, w22, n/4, CC);
        n = LLAYERS*CC*HFF_;
        k_split_w4<<<(n/4+255)/256, 256>>>(w3, w32, n/4, HFF_);
    }

    k_input_proj<<<MM*CC/256, 256>>>(x, w_in, h);

    for (int l = 0; l < LLAYERS; ++l) {
        const __half* wqkv_l = wqkv2 + (size_t)l*3*CC*2*CC;
        const __half* wo_l   = wo2   + (size_t)l*CC*2*CC;
        const __half* w1_l   = w12   + (size_t)l*HFF_*2*CC;
        const __half* w2_l   = w22   + (size_t)l*HFF_*2*CC;
        const __half* w3_l   = w32   + (size_t)l*CC*2*HFF_;

        // --- attention block ---
        k_rms_h<<<MM, 256>>>(h, a2, g1 + l*CC);
        k_hgemm<false><<<dim3(3*CC/128, MM/128), 256, GSMEM>>>(a2, wqkv_l, qkvb, MM, 3*CC, CC);
        k_rope_cvt<<<(MM*512)/256, 256>>>(qkvb, qhp, qlp, khp, klp, vthp, vtlp);
        k_attn_mma<<<dim3(TT/64, NHH, BB), 128, ASMEM>>>(qhp, qlp, khp, klp, vthp, vtlp, y2);
        k_hgemm<true><<<dim3(CC/128, MM/128), 256, GSMEM>>>(y2, wo_l, h, MM, CC, CC);

        // --- MLP block ---
        k_rms_h<<<MM, 256>>>(h, a2, g2 + l*CC);
        k_hgemm<false><<<dim3(HFF_/128, MM/128), 256, GSMEM>>>(a2, w1_l, u1, MM, HFF_, CC);
        k_hgemm<false><<<dim3(HFF_/128, MM/128), 256, GSMEM>>>(a2, w2_l, u2, MM, HFF_, CC);
        k_silu_h4<<<(MM*HFF_/4+255)/256, 256>>>(u1, u2, u12);
        k_hgemm<true><<<dim3(CC/128, MM/128), 256, GSMEM>>>(u12, w3_l, h, MM, CC, HFF_);
    }

    k_rms_out4<<<MM, 256>>>(h, out, gf);
}